// round 3
// baseline (speedup 1.0000x reference)
#include <cuda_runtime.h>
#include <cstdint>

// ---------------------------------------------------------------------------
// AdvancedMixConsole: batched radix-16/8 Stockham FFT mixing console
// ---------------------------------------------------------------------------

#define SRATE    44100.0f
#define S_LEN    262144
#define NFFT     524288
#define NL       131072
#define REVN     65536
#define NOISE_LEN 66558
#define TAPSM1   1022
#define NSIG     32          // BS*NT
#define PI_F     3.14159265358979323846f

// ------------------------------ scratch (static device, no allocation) -----
__device__ float2 g_A[(size_t)NSIG * NFFT];   // 134 MB
__device__ float2 g_B[(size_t)NSIG * NFFT];   // 134 MB
__device__ float2 g_C[(size_t)48 * NL];       // 50 MB
__device__ float2 g_D[(size_t)48 * NL];       // 50 MB
__device__ float2 g_E[(size_t)12 * NL];       // 12.6 MB
__device__ float2 g_F[(size_t)12 * NL];       // 12.6 MB
__device__ float  g_x[(size_t)NSIG * S_LEN];  // 33.5 MB (time-domain work)
__device__ float  g_pan[(size_t)64 * S_LEN];  // 67 MB (BS,2,NT,SEQ)
__device__ float  g_ms[(size_t)4 * S_LEN];    // master (BS,2,SEQ)
__device__ float  g_fx[(size_t)4 * S_LEN];    // fx send bus
__device__ float  g_ir[(size_t)4 * REVN];     // reverb IR
__device__ float  g_tpd[NSIG * 27];
__device__ float  g_mpd[2 * 26];
__device__ float  g_eqT[NSIG * 36];           // 6 filters x (b0,b1,b2,1,a1,a2)
__device__ float  g_eqM[2 * 36];

// ------------------------------ parameter ranges ---------------------------
__constant__ float c_TR[54] = {
  -48.f,48.f,
  -12.f,12.f, 20.f,2000.f, 0.1f,5.f,
  -12.f,12.f, 80.f,2000.f, 0.1f,5.f,
  -12.f,12.f, 2000.f,8000.f, 0.1f,5.f,
  -12.f,12.f, 8000.f,12000.f, 0.1f,5.f,
  -12.f,12.f, 12000.f,21050.f, 0.1f,5.f,
  -12.f,12.f, 6000.f,21050.f, 0.1f,5.f,
  -60.f,0.f, 1.f,10.f, 5.f,250.f, 10.f,250.f, 3.f,12.f, 0.f,6.f,
  -80.f,12.f, 0.f,1.f
};
__constant__ float c_MR[52] = {
  -48.f,48.f,
  -12.f,12.f, 20.f,2000.f, 0.1f,5.f,
  -12.f,12.f, 80.f,2000.f, 0.1f,5.f,
  -12.f,12.f, 2000.f,8000.f, 0.1f,5.f,
  -12.f,12.f, 8000.f,12000.f, 0.1f,5.f,
  -12.f,12.f, 12000.f,21050.f, 0.1f,5.f,
  -12.f,12.f, 6000.f,21050.f, 0.1f,5.f,
  -60.f,0.f, 1.f,10.f, 5.f,250.f, 10.f,250.f, 3.f,12.f, 0.f,6.f,
  -48.f,48.f
};

__device__ __forceinline__ float2 cadd(float2 a, float2 b) { return make_float2(a.x+b.x, a.y+b.y); }
__device__ __forceinline__ float2 csub(float2 a, float2 b) { return make_float2(a.x-b.x, a.y-b.y); }
__device__ __forceinline__ float2 cmulf(float2 a, float2 b) {
  return make_float2(a.x*b.x - a.y*b.y, a.x*b.y + a.y*b.x);
}
// a * (sg * i)
__device__ __forceinline__ float2 cmuli(float2 a, float sg) { return make_float2(-sg*a.y, sg*a.x); }

// 4-point DFT in place, natural output order. sign sg: e^{sg*i*2pi*k/4}
__device__ __forceinline__ void fft4(float2& x0, float2& x1, float2& x2, float2& x3, float sg) {
  float2 t0 = cadd(x0, x2), t1 = csub(x0, x2);
  float2 t2 = cadd(x1, x3), t3 = cmuli(csub(x1, x3), sg);
  x0 = cadd(t0, t2); x2 = csub(t0, t2);
  x1 = cadd(t1, t3); x3 = csub(t1, t3);
}

#define FC1 0.9238795325112867f   // cos(pi/8)
#define FS1 0.3826834323650898f   // sin(pi/8)
#define FC2 0.7071067811865476f   // cos(pi/4)

// ------------------------------ Stockham radix-16 pass ---------------------
__global__ void __launch_bounds__(256) k_fft16(float2* __restrict__ dst,
                                               const float2* __restrict__ src,
                                               int N, int s, int total, float sg) {
  int idx = blockIdx.x * blockDim.x + threadIdx.x;
  if (idx >= total) return;
  int per = N >> 4;
  int b = idx / per;
  int j = idx - b * per;
  int p = j / s, q = j - p * s;
  const float2* x = src + (size_t)b * N + q + (size_t)s * p;
  float2 v[16];
#pragma unroll
  for (int r = 0; r < 16; r++) v[r] = x[(size_t)r * per];

  // stage 1: fft4 across stride-4 columns; store c[r][n] at v[4r+n]
#pragma unroll
  for (int n = 0; n < 4; n++) {
    float2 a0 = v[n], a1 = v[n+4], a2 = v[n+8], a3 = v[n+12];
    fft4(a0, a1, a2, a3, sg);
    v[n] = a0; v[n+4] = a1; v[n+8] = a2; v[n+12] = a3;
  }
  // inner twiddles: v[4r+n] *= W16^{n*r}
  v[5]  = cmulf(v[5],  make_float2( FC1,  sg*FS1));   // W16^1
  v[6]  = cmulf(v[6],  make_float2( FC2,  sg*FC2));   // W16^2
  v[7]  = cmulf(v[7],  make_float2( FS1,  sg*FC1));   // W16^3
  v[9]  = cmulf(v[9],  make_float2( FC2,  sg*FC2));   // W16^2
  v[10] = cmuli(v[10], sg);                           // W16^4
  v[11] = cmulf(v[11], make_float2(-FC2,  sg*FC2));   // W16^6
  v[13] = cmulf(v[13], make_float2( FS1,  sg*FC1));   // W16^3
  v[14] = cmulf(v[14], make_float2(-FC2,  sg*FC2));   // W16^6
  v[15] = cmulf(v[15], make_float2(-FC1, -sg*FS1));   // W16^9

  // stage 2: fft4 over contiguous quads (gives D[r][k'] in natural k')
  fft4(v[0],  v[1],  v[2],  v[3],  sg);
  fft4(v[4],  v[5],  v[6],  v[7],  sg);
  fft4(v[8],  v[9],  v[10], v[11], sg);
  fft4(v[12], v[13], v[14], v[15], sg);

  // external twiddle + digit-reversed write: X[m] = v[((m&3)<<2)|(m>>2)] * W_N^{m p s}
  float2* y = dst + (size_t)b * N + q + (size_t)16 * s * p;
  float base = __int2float_rn(2 * p * s) / __int2float_rn(N);
  float sb, cb; sincospif(base, &sb, &cb);
  float2 w1 = make_float2(cb, sg*sb);
  float s4b, c4b; sincospif(4.f * base, &s4b, &c4b);
  float2 w4 = make_float2(c4b, sg*s4b);
  float2 wrow = make_float2(1.f, 0.f);
  float2 wm = make_float2(1.f, 0.f);
#pragma unroll
  for (int m = 0; m < 16; m++) {
    int slot = ((m & 3) << 2) | (m >> 2);
    y[(size_t)m * s] = cmulf(v[slot], wm);
    if ((m & 3) == 3) { wrow = cmulf(wrow, w4); wm = wrow; }
    else               wm = cmulf(wm, w1);
  }
}

// ------------------------------ Stockham radix-8 pass ----------------------
__global__ void __launch_bounds__(256) k_fft8(float2* __restrict__ dst,
                                              const float2* __restrict__ src,
                                              int N, int s, int total, float sg) {
  int idx = blockIdx.x * blockDim.x + threadIdx.x;
  if (idx >= total) return;
  int per = N >> 3;
  int b = idx / per;
  int j = idx - b * per;
  int p = j / s, q = j - p * s;
  const float2* x = src + (size_t)b * N + q + (size_t)s * p;
  float2 v[8];
#pragma unroll
  for (int r = 0; r < 8; r++) v[r] = x[(size_t)r * per];

  // stage 1: a[n]=v[n]+v[n+4] -> v[0..3];  b[n]=(v[n]-v[n+4])*W8^n -> v[4..7]
  {
    float2 d0 = csub(v[0], v[4]);
    float2 d1 = csub(v[1], v[5]);
    float2 d2 = csub(v[2], v[6]);
    float2 d3 = csub(v[3], v[7]);
    v[0] = cadd(v[0], v[4]);
    v[1] = cadd(v[1], v[5]);
    v[2] = cadd(v[2], v[6]);
    v[3] = cadd(v[3], v[7]);
    v[4] = d0;
    v[5] = cmulf(d1, make_float2( FC2, sg*FC2));
    v[6] = cmuli(d2, sg);
    v[7] = cmulf(d3, make_float2(-FC2, sg*FC2));
  }
  fft4(v[0], v[1], v[2], v[3], sg);
  fft4(v[4], v[5], v[6], v[7], sg);

  float2* y = dst + (size_t)b * N + q + (size_t)8 * s * p;
  float base = __int2float_rn(2 * p * s) / __int2float_rn(N);
  float sb, cb; sincospif(base, &sb, &cb);
  float2 w1 = make_float2(cb, sg*sb);
  float2 wm = make_float2(1.f, 0.f);
#pragma unroll
  for (int m = 0; m < 8; m++) {
    int slot = ((m & 1) << 2) | (m >> 1);
    y[(size_t)m * s] = cmulf(v[slot], wm);
    wm = cmulf(wm, w1);
  }
}

// ------------------------------ Stockham radix-2 pass (tail) ---------------
__global__ void k_fft2(float2* __restrict__ dst, const float2* __restrict__ src,
                       int N, int nCur, int s, int total, float sign) {
  int idx = blockIdx.x * blockDim.x + threadIdx.x;
  if (idx >= total) return;
  int half = N >> 1;
  int b = idx / half;
  int j = idx - b * half;
  int p = j / s;
  int q = j - p * s;
  const float2* x = src + (size_t)b * N;
  float2*       y = dst + (size_t)b * N;
  float2 a = x[q + s*p];
  float2 c = x[q + s*p + half];
  float u = __int2float_rn(2*p) / __int2float_rn(nCur);
  float sp, cp; sincospif(u, &sp, &cp);
  float wr = cp, wi = sign * sp;
  float2 sum = make_float2(a.x + c.x, a.y + c.y);
  float dr = a.x - c.x, di = a.y - c.y;
  float2 od = make_float2(dr*wr - di*wi, dr*wi + di*wr);
  int o = q + 2*s*p;
  y[o]     = sum;
  y[o + s] = od;
}

// ------------------------------ biquad coefficient builder -----------------
__device__ void biquad_coef(int ftype, float g, float fc, float q, float* out) {
  float A  = exp10f(g * (1.f/40.f));
  float w0 = 2.f * PI_F * fc / SRATE;
  float sw, cw; sincosf(w0, &sw, &cw);
  float al = sw / (2.f * q);
  float sA = sqrtf(A);
  float b0,b1,b2,a0,a1,a2;
  if (ftype == 0) {            // low shelf
    b0 =  A*((A+1.f) - (A-1.f)*cw + 2.f*sA*al);
    b1 =  2.f*A*((A-1.f) - (A+1.f)*cw);
    b2 =  A*((A+1.f) - (A-1.f)*cw - 2.f*sA*al);
    a0 =  (A+1.f) + (A-1.f)*cw + 2.f*sA*al;
    a1 = -2.f*((A-1.f) + (A+1.f)*cw);
    a2 =  (A+1.f) + (A-1.f)*cw - 2.f*sA*al;
  } else if (ftype == 2) {     // high shelf
    b0 =  A*((A+1.f) + (A-1.f)*cw + 2.f*sA*al);
    b1 = -2.f*A*((A-1.f) + (A+1.f)*cw);
    b2 =  A*((A+1.f) + (A-1.f)*cw - 2.f*sA*al);
    a0 =  (A+1.f) - (A-1.f)*cw + 2.f*sA*al;
    a1 =  2.f*((A-1.f) - (A+1.f)*cw);
    a2 =  (A+1.f) - (A-1.f)*cw - 2.f*sA*al;
  } else {                     // peaking
    b0 = 1.f + al*A; b1 = -2.f*cw; b2 = 1.f - al*A;
    a0 = 1.f + al/A; a1 = -2.f*cw; a2 = 1.f - al/A;
  }
  float inv = 1.f / a0;
  out[0] = b0*inv; out[1] = b1*inv; out[2] = b2*inv;
  out[3] = 1.f;    out[4] = a1*inv; out[5] = a2*inv;
}

__global__ void k_prep(const float* __restrict__ tp, const float* __restrict__ mp) {
  int tid = threadIdx.x;
  for (int i = tid; i < NSIG*27; i += blockDim.x) {
    int j = i % 27;
    g_tpd[i] = tp[i] * (c_TR[2*j+1] - c_TR[2*j]) + c_TR[2*j];
  }
  for (int i = tid; i < 2*26; i += blockDim.x) {
    int j = i % 26;
    g_mpd[i] = mp[i] * (c_MR[2*j+1] - c_MR[2*j]) + c_MR[2*j];
  }
  __syncthreads();
  for (int i = tid; i < NSIG*6; i += blockDim.x) {
    int s = i / 6, k = i % 6;
    int ft = (k == 0) ? 0 : ((k == 5) ? 2 : 1);
    biquad_coef(ft, g_tpd[s*27+1+3*k], g_tpd[s*27+2+3*k], g_tpd[s*27+3+3*k], &g_eqT[i*6]);
  }
  for (int i = tid; i < 2*6; i += blockDim.x) {
    int s = i / 6, k = i % 6;
    int ft = (k == 0) ? 0 : ((k == 5) ? 2 : 1);
    biquad_coef(ft, g_mpd[s*26+1+3*k], g_mpd[s*26+2+3*k], g_mpd[s*26+3+3*k], &g_eqM[i*6]);
  }
}

// ------------------------------ pack kernels -------------------------------
__global__ void k_pack_track(float2* __restrict__ dst, const float* __restrict__ tracks) {
  int idx = blockIdx.x * blockDim.x + threadIdx.x;
  if (idx >= NSIG * NFFT) return;
  int s = idx / NFFT, i = idx - s * NFFT;
  float v = 0.f;
  if (i < S_LEN) {
    float g = exp10f(g_tpd[s*27 + 0] * 0.05f);
    v = tracks[(size_t)s*S_LEN + i] * g;
    g_x[(size_t)s*S_LEN + i] = v;
  }
  dst[idx] = make_float2(v, 0.f);
}

// ------------------------------ EQ spectral multiply -----------------------
__global__ void k_eqmul(float2* __restrict__ X, const float* __restrict__ coefs,
                        int nsig, int sigdiv, int N) {
  int nf = (N >> 1) + 1;
  int idx = blockIdx.x * blockDim.x + threadIdx.x;
  if (idx >= nsig * nf) return;
  int s = idx / nf, k = idx - s * nf;
  float u = __int2float_rn(2*k) / __int2float_rn(N);
  float s1, c1; sincospif(u, &s1, &c1);     // z1 = e^{-iw} = (c1, -s1)
  float z2r = c1*c1 - s1*s1;
  float z2i = -2.f * c1 * s1;
  float hr = 1.f, hi = 0.f;
  const float* cf = coefs + (s / sigdiv) * 36;
#pragma unroll
  for (int f = 0; f < 6; f++) {
    float b0 = cf[f*6+0], b1 = cf[f*6+1], b2 = cf[f*6+2];
    float a1 = cf[f*6+4], a2 = cf[f*6+5];
    float nr = b0 + b1*c1 + b2*z2r;
    float ni = -b1*s1 + b2*z2i;
    float dr = 1.f + a1*c1 + a2*z2r;
    float di = -a1*s1 + a2*z2i;
    float inv = 1.f / (dr*dr + di*di);
    float rr = (nr*dr + ni*di) * inv;
    float ri = (ni*dr - nr*di) * inv;
    float t = hr*rr - hi*ri; hi = hr*ri + hi*rr; hr = t;
  }
  float2* xp = X + (size_t)s * N;
  float2 v = xp[k];
  xp[k] = make_float2(v.x*hr - v.y*hi, v.x*hi + v.y*hr);
  int half = N >> 1;
  if (k > 0 && k < half) {
    float2 w2 = xp[N - k];
    xp[N - k] = make_float2(w2.x*hr + w2.y*hi, -w2.x*hi + w2.y*hr);  // conj(H)
  }
}

// ------------------------------ compressor: gain computer ------------------
__global__ void k_compgc(const float2* __restrict__ src, float2* __restrict__ dst,
                         float* __restrict__ xstore, const float* __restrict__ pd,
                         int pstride, int sigdiv, int nsig, int N) {
  int idx = blockIdx.x * blockDim.x + threadIdx.x;
  if (idx >= nsig * N) return;
  int s = idx / N, i = idx - s * N;
  float gc = 0.f;
  if (i < S_LEN) {
    float invN = 1.f / (float)N;
    float x = src[(size_t)s*N + i].x * invN;
    xstore[(size_t)s*S_LEN + i] = x;
    const float* pp = pd + (s / sigdiv) * pstride + 19;
    float th = pp[0], ratio = pp[1], knee = pp[4];
    float ax = fabsf(x); if (ax < 1e-8f) ax = 1e-8f;
    float xdb = 20.f * log10f(ax);
    float d = xdb - th;
    if (2.f*d < -knee)             gc = 0.f;
    else if (2.f*fabsf(d) <= knee) { float e = d + 0.5f*knee; gc = (1.f/ratio - 1.f)*e*e/(2.f*knee); }
    else                           gc = d/ratio - d;
  }
  dst[(size_t)s*N + i] = make_float2(gc, 0.f);
}

// ------------------------------ compressor smoothing filter ----------------
__global__ void k_compmul(float2* __restrict__ X, const float* __restrict__ pd,
                          int pstride, int sigdiv, int nsig, int N) {
  int nf = (N >> 1) + 1;
  int idx = blockIdx.x * blockDim.x + threadIdx.x;
  if (idx >= nsig * nf) return;
  int s = idx / nf, k = idx - s * nf;
  float at    = pd[(s / sigdiv) * pstride + 21];
  float alpha = expf(-logf(9.f) / (SRATE * at * 0.001f));
  float u = __int2float_rn(2*k) / __int2float_rn(N);
  float s1, c1; sincospif(u, &s1, &c1);
  float dr = 1.f - alpha*c1;
  float di = alpha*s1;
  float inv = (1.f - alpha) / (dr*dr + di*di);
  float hr = dr * inv, hi = -di * inv;
  float2* xp = X + (size_t)s * N;
  float2 v = xp[k];
  xp[k] = make_float2(v.x*hr - v.y*hi, v.x*hi + v.y*hr);
  int half = N >> 1;
  if (k > 0 && k < half) {
    float2 w2 = xp[N - k];
    xp[N - k] = make_float2(w2.x*hr + w2.y*hi, -w2.x*hi + w2.y*hr);
  }
}

// ------------------------------ apply comp gain + pan ----------------------
__global__ void k_applypan(const float2* __restrict__ gsb) {
  int idx = blockIdx.x * blockDim.x + threadIdx.x;
  if (idx >= NSIG * S_LEN) return;
  int s = idx / S_LEN, i = idx - s * S_LEN;
  float invN = 1.f / (float)NFFT;
  int j = i + 2048; if (j > S_LEN - 1) j = S_LEN - 1;
  float gs = gsb[(size_t)s*NFFT + j].x * invN;
  float makeup = g_tpd[s*27 + 24];
  float val = g_x[(size_t)s*S_LEN + i] * exp10f((gs + makeup) * 0.05f);
  float theta = g_tpd[s*27 + 26] * (PI_F * 0.5f);
  float gl = sqrtf(fmaxf((PI_F*0.5f - theta) * (2.f/PI_F) * cosf(theta), 0.f));
  float gr = sqrtf(fmaxf(theta * (2.f/PI_F) * sinf(theta), 0.f));
  int b = s >> 4, t = s & 15;
  g_pan[((size_t)(b*2+0)*16 + t)*S_LEN + i] = val * gl;
  g_pan[((size_t)(b*2+1)*16 + t)*S_LEN + i] = val * gr;
}

__global__ void k_mix() {
  int idx = blockIdx.x * blockDim.x + threadIdx.x;
  if (idx >= 4 * S_LEN) return;
  int u = idx / S_LEN, i = idx - u * S_LEN;
  int b = u >> 1;
  float ms = 0.f, fs = 0.f;
#pragma unroll
  for (int t = 0; t < 16; t++) {
    float v = g_pan[((size_t)u*16 + t)*S_LEN + i];
    ms += v;
    fs += v * exp10f(g_tpd[(b*16 + t)*27 + 25] * 0.05f);
  }
  g_ms[(size_t)u*S_LEN + i] = ms;
  g_fx[(size_t)u*S_LEN + i] = fs;
}

__global__ void k_copypan(float* __restrict__ out) {
  int idx = blockIdx.x * blockDim.x + threadIdx.x;
  if (idx >= 64 * S_LEN) return;
  out[idx] = g_pan[idx];
}

// ------------------------------ reverb -------------------------------------
__global__ void k_packnoise(float2* __restrict__ dst, const float* __restrict__ noise) {
  int idx = blockIdx.x * blockDim.x + threadIdx.x;
  if (idx >= 48 * NL) return;
  int s2 = idx / NL, i = idx - s2 * NL;
  float v = (i < NOISE_LEN) ? noise[(size_t)s2*NOISE_LEN + i] : 0.f;
  dst[idx] = make_float2(v, 0.f);
}

__global__ void k_packfb(float2* __restrict__ dst, const float* __restrict__ fb) {
  int idx = blockIdx.x * blockDim.x + threadIdx.x;
  if (idx >= 12 * NL) return;
  int k = idx / NL, i = idx - k * NL;
  float v = (i < 1023) ? fb[k*1023 + i] : 0.f;
  dst[idx] = make_float2(v, 0.f);
}

__global__ void k_revmul(float2* __restrict__ Dp, const float2* __restrict__ Fp) {
  int idx = blockIdx.x * blockDim.x + threadIdx.x;
  if (idx >= 48 * NL) return;
  int s2 = idx / NL, j = idx - s2 * NL;
  int k = s2 % 12;
  Dp[idx] = cmulf(Dp[idx], Fp[(size_t)k*NL + j]);
}

__global__ void k_buildir(const float2* __restrict__ Cp, const float* __restrict__ fxp) {
  int idx = blockIdx.x * blockDim.x + threadIdx.x;
  if (idx >= 4 * REVN) return;
  int u = idx / REVN, i = idx - u * REVN;
  int b = u >> 1;
  float invnL = 1.f / (float)NL;
  float tt = (float)i * (1.f / 65535.f);
  float acc = 0.f;
#pragma unroll
  for (int k = 0; k < 12; k++) {
    float dec  = fxp[b*25 + 12 + k] * 10.f + 1.f;
    float gn   = fxp[b*25 + k];
    float filt = Cp[((size_t)(u*12 + k))*NL + TAPSM1 + i].x * invnL;
    acc += filt * expf(-dec * tt) * gn;
  }
  g_ir[(size_t)u*REVN + i] = acc * (1.f / 12.f);
}

__global__ void k_packwet(float2* __restrict__ dst) {
  int idx = blockIdx.x * blockDim.x + threadIdx.x;
  if (idx >= 8 * NFFT) return;
  int u = idx / NFFT, i = idx - u * NFFT;
  float v;
  if (u < 4) v = (i < S_LEN) ? g_fx[(size_t)u*S_LEN + i] : 0.f;
  else       v = (i < REVN)  ? g_ir[(size_t)(u-4)*REVN + i] : 0.f;
  dst[idx] = make_float2(v, 0.f);
}

__global__ void k_wetmul(float2* __restrict__ Bp) {
  int idx = blockIdx.x * blockDim.x + threadIdx.x;
  if (idx >= 4 * NFFT) return;
  int u = idx / NFFT, j = idx - u * NFFT;
  Bp[(size_t)u*NFFT + j] = cmulf(Bp[(size_t)u*NFFT + j], Bp[(size_t)(u+4)*NFFT + j]);
}

__global__ void k_addrev(const float2* __restrict__ Ap, const float* __restrict__ fxp) {
  int idx = blockIdx.x * blockDim.x + threadIdx.x;
  if (idx >= 4 * S_LEN) return;
  int u = idx / S_LEN, i = idx - u * S_LEN;
  int b = u >> 1;
  float wet = Ap[(size_t)u*NFFT + i].x * (1.f / (float)NFFT);
  float m = fxp[b*25 + 24];
  g_ms[(size_t)u*S_LEN + i] += (1.f - m) * g_fx[(size_t)u*S_LEN + i] + m * wet;
}

// ------------------------------ master chain -------------------------------
__global__ void k_packmaster(float2* __restrict__ dst) {
  int idx = blockIdx.x * blockDim.x + threadIdx.x;
  if (idx >= 4 * NFFT) return;
  int u = idx / NFFT, i = idx - u * NFFT;
  int b = u >> 1;
  float g = exp10f(g_mpd[b*26 + 0] * 0.05f);
  float v = (i < S_LEN) ? g_ms[(size_t)u*S_LEN + i] * g : 0.f;
  dst[idx] = make_float2(v, 0.f);
}

__global__ void k_final(const float2* __restrict__ gsb, float* __restrict__ out, long long off) {
  int idx = blockIdx.x * blockDim.x + threadIdx.x;
  if (idx >= 4 * S_LEN) return;
  int u = idx / S_LEN, i = idx - u * S_LEN;
  int b = u >> 1;
  int j = i + 1024; if (j > S_LEN - 1) j = S_LEN - 1;
  float gs = gsb[(size_t)u*NFFT + j].x * (1.f / (float)NFFT);
  float makeup = g_mpd[b*26 + 24];
  float og = exp10f(g_mpd[b*26 + 25] * 0.05f);
  out[off + (size_t)u*S_LEN + i] = g_x[(size_t)u*S_LEN + i] * exp10f((gs + makeup) * 0.05f) * og;
}

// ------------------------------ host side ----------------------------------
static inline int grid1(long long n) { return (int)((n + 255) / 256); }

// N = 2^19: passes [16,16,16,16,8] -> 5 passes, result lands on the 'b' side chain
static float2* fft_run_big(float2* a, float2* b, int batch, float sg) {
  float2* src = a; float2* dst = b;
  int s = 1;
  for (int i = 0; i < 4; i++) {
    int total = batch * (NFFT >> 4);
    k_fft16<<<grid1(total), 256>>>(dst, src, NFFT, s, total, sg);
    float2* t = src; src = dst; dst = t;
    s <<= 4;
  }
  {
    int total = batch * (NFFT >> 3);
    k_fft8<<<grid1(total), 256>>>(dst, src, NFFT, s, total, sg);
    float2* t = src; src = dst; dst = t;
  }
  return src;   // last-written buffer
}

// N = 2^17: passes [16,16,16,16,2] -> 5 passes
static float2* fft_run_nl(float2* a, float2* b, int batch, float sg) {
  float2* src = a; float2* dst = b;
  int s = 1;
  for (int i = 0; i < 4; i++) {
    int total = batch * (NL >> 4);
    k_fft16<<<grid1(total), 256>>>(dst, src, NL, s, total, sg);
    float2* t = src; src = dst; dst = t;
    s <<= 4;
  }
  {
    int total = batch * (NL >> 1);
    k_fft2<<<grid1(total), 256>>>(dst, src, NL, NL / s, s, total, sg);
    float2* t = src; src = dst; dst = t;
  }
  return src;
}

extern "C" void kernel_launch(void* const* d_in, const int* in_sizes, int n_in,
                              void* d_out, int out_size) {
  const float* tracks        = (const float*)d_in[0];
  const float* track_params  = (const float*)d_in[1];
  const float* fxp           = (const float*)d_in[2];
  const float* master_params = (const float*)d_in[3];
  const float* noise         = (const float*)d_in[4];
  const float* fb            = (const float*)d_in[5];
  float* out = (float*)d_out;

  float2 *A, *B, *C, *D, *E, *F;
  float *eqT, *eqM, *tpd, *mpd, *xb;
  cudaGetSymbolAddress((void**)&A, g_A);
  cudaGetSymbolAddress((void**)&B, g_B);
  cudaGetSymbolAddress((void**)&C, g_C);
  cudaGetSymbolAddress((void**)&D, g_D);
  cudaGetSymbolAddress((void**)&E, g_E);
  cudaGetSymbolAddress((void**)&F, g_F);
  cudaGetSymbolAddress((void**)&eqT, g_eqT);
  cudaGetSymbolAddress((void**)&eqM, g_eqM);
  cudaGetSymbolAddress((void**)&tpd, g_tpd);
  cudaGetSymbolAddress((void**)&mpd, g_mpd);
  cudaGetSymbolAddress((void**)&xb,  g_x);

  k_prep<<<1, 256>>>(track_params, master_params);

  // ---- per-track: gain -> EQ -> compressor -> pan ----
  k_pack_track<<<grid1((long long)NSIG*NFFT), 256>>>(A, tracks);
  float2* r = fft_run_big(A, B, NSIG, -1.f);
  k_eqmul<<<grid1((long long)NSIG*(NFFT/2+1)), 256>>>(r, eqT, NSIG, 1, NFFT);
  float2* r2 = fft_run_big(r, (r == A) ? B : A, NSIG, 1.f);
  float2* r2o = (r2 == A) ? B : A;
  k_compgc<<<grid1((long long)NSIG*NFFT), 256>>>(r2, r2o, xb, tpd, 27, 1, NSIG, NFFT);
  float2* r3 = fft_run_big(r2o, r2, NSIG, -1.f);
  k_compmul<<<grid1((long long)NSIG*(NFFT/2+1)), 256>>>(r3, tpd, 27, 1, NSIG, NFFT);
  float2* r4 = fft_run_big(r3, (r3 == A) ? B : A, NSIG, 1.f);
  k_applypan<<<grid1((long long)NSIG*S_LEN), 256>>>(r4);
  k_mix<<<grid1((long long)4*S_LEN), 256>>>();

  long long PAN = (long long)64 * S_LEN;
  long long moff = 0;
  if ((long long)out_size >= PAN + 4LL*S_LEN) {
    k_copypan<<<grid1(PAN), 256>>>(out);
    moff = PAN;
  }

  // ---- reverb IR build ----
  k_packnoise<<<grid1((long long)48*NL), 256>>>(C, noise);
  float2* rn = fft_run_nl(C, D, 48, -1.f);
  k_packfb<<<grid1((long long)12*NL), 256>>>(E, fb);
  float2* rf = fft_run_nl(E, F, 12, -1.f);
  k_revmul<<<grid1((long long)48*NL), 256>>>(rn, rf);
  float2* ri = fft_run_nl(rn, (rn == C) ? D : C, 48, 1.f);
  k_buildir<<<grid1((long long)4*REVN), 256>>>(ri, fxp);

  // ---- wet convolution: fx_in (*) ir ----
  k_packwet<<<grid1((long long)8*NFFT), 256>>>(A);
  float2* rw = fft_run_big(A, B, 8, -1.f);
  k_wetmul<<<grid1((long long)4*NFFT), 256>>>(rw);
  float2* rw2 = fft_run_big(rw, (rw == A) ? B : A, 4, 1.f);
  k_addrev<<<grid1((long long)4*S_LEN), 256>>>(rw2, fxp);

  // ---- master chain: gain -> EQ -> comp -> gain ----
  k_packmaster<<<grid1((long long)4*NFFT), 256>>>(A);
  float2* m1 = fft_run_big(A, B, 4, -1.f);
  k_eqmul<<<grid1((long long)4*(NFFT/2+1)), 256>>>(m1, eqM, 4, 2, NFFT);
  float2* m2 = fft_run_big(m1, (m1 == A) ? B : A, 4, 1.f);
  float2* m2o = (m2 == A) ? B : A;
  k_compgc<<<grid1((long long)4*NFFT), 256>>>(m2, m2o, xb, mpd, 26, 2, 4, NFFT);
  float2* m3 = fft_run_big(m2o, m2, 4, -1.f);
  k_compmul<<<grid1((long long)4*(NFFT/2+1)), 256>>>(m3, mpd, 26, 2, 4, NFFT);
  float2* m4 = fft_run_big(m3, (m3 == A) ? B : A, 4, 1.f);
  k_final<<<grid1((long long)4*S_LEN), 256>>>(m4, out, moff);
}

// round 4
// speedup vs baseline: 1.9916x; 1.9916x over previous
#include <cuda_runtime.h>
#include <cstdint>

// ---------------------------------------------------------------------------
// AdvancedMixConsole: paired-real radix-16 Stockham FFT mixing console
// Two real signals packed per complex FFT everywhere.
// ---------------------------------------------------------------------------

#define SRATE    44100.0f
#define S_LEN    262144
#define NFFT     524288
#define NL       131072
#define REVN     65536
#define NOISE_LEN 66558
#define TAPSM1   1022
#define NSIG     32          // BS*NT
#define NPAIR    16
#define PI_F     3.14159265358979323846f

// ------------------------------ scratch (static device, no allocation) -----
__device__ float2 g_A[(size_t)NPAIR * NFFT];   // 67 MB
__device__ float2 g_B[(size_t)NPAIR * NFFT];   // 67 MB
__device__ float2 g_C[(size_t)24 * NL];        // 25 MB  (noise pairs)
__device__ float2 g_D[(size_t)24 * NL];        // 25 MB
__device__ float2 g_E[(size_t)6 * NL];         // 6.3 MB (fb pairs)
__device__ float2 g_F[(size_t)6 * NL];         // 6.3 MB
__device__ float2 g_x[(size_t)NPAIR * S_LEN];  // 33.5 MB paired post-EQ time
__device__ float2 g_xm[(size_t)2 * S_LEN];     // master post-EQ time (paired L/R)
__device__ float  g_pan[(size_t)64 * S_LEN];   // fallback pan buffer
__device__ float  g_ms[(size_t)4 * S_LEN];     // master bus (BS,2,SEQ)
__device__ float  g_fx[(size_t)4 * S_LEN];     // fx send bus
__device__ float  g_ir[(size_t)4 * REVN];      // reverb IR
__device__ float  g_tpd[NSIG * 27];
__device__ float  g_mpd[2 * 26];
__device__ float  g_eqT[NSIG * 36];
__device__ float  g_eqM[2 * 36];
__device__ float  g_gain[NSIG];                // input gain (linear)
__device__ float  g_send[NSIG];                // send gain (linear)
__device__ float  g_gl[NSIG];                  // pan left gain
__device__ float  g_gr[NSIG];                  // pan right gain

// ------------------------------ parameter ranges ---------------------------
__constant__ float c_TR[54] = {
  -48.f,48.f,
  -12.f,12.f, 20.f,2000.f, 0.1f,5.f,
  -12.f,12.f, 80.f,2000.f, 0.1f,5.f,
  -12.f,12.f, 2000.f,8000.f, 0.1f,5.f,
  -12.f,12.f, 8000.f,12000.f, 0.1f,5.f,
  -12.f,12.f, 12000.f,21050.f, 0.1f,5.f,
  -12.f,12.f, 6000.f,21050.f, 0.1f,5.f,
  -60.f,0.f, 1.f,10.f, 5.f,250.f, 10.f,250.f, 3.f,12.f, 0.f,6.f,
  -80.f,12.f, 0.f,1.f
};
__constant__ float c_MR[52] = {
  -48.f,48.f,
  -12.f,12.f, 20.f,2000.f, 0.1f,5.f,
  -12.f,12.f, 80.f,2000.f, 0.1f,5.f,
  -12.f,12.f, 2000.f,8000.f, 0.1f,5.f,
  -12.f,12.f, 8000.f,12000.f, 0.1f,5.f,
  -12.f,12.f, 12000.f,21050.f, 0.1f,5.f,
  -12.f,12.f, 6000.f,21050.f, 0.1f,5.f,
  -60.f,0.f, 1.f,10.f, 5.f,250.f, 10.f,250.f, 3.f,12.f, 0.f,6.f,
  -48.f,48.f
};

__device__ __forceinline__ float2 cadd(float2 a, float2 b) { return make_float2(a.x+b.x, a.y+b.y); }
__device__ __forceinline__ float2 csub(float2 a, float2 b) { return make_float2(a.x-b.x, a.y-b.y); }
__device__ __forceinline__ float2 cmulf(float2 a, float2 b) {
  return make_float2(a.x*b.x - a.y*b.y, a.x*b.y + a.y*b.x);
}
__device__ __forceinline__ float2 cmuli(float2 a, float sg) { return make_float2(-sg*a.y, sg*a.x); }

__device__ __forceinline__ void fft4(float2& x0, float2& x1, float2& x2, float2& x3, float sg) {
  float2 t0 = cadd(x0, x2), t1 = csub(x0, x2);
  float2 t2 = cadd(x1, x3), t3 = cmuli(csub(x1, x3), sg);
  x0 = cadd(t0, t2); x2 = csub(t0, t2);
  x1 = cadd(t1, t3); x3 = csub(t1, t3);
}

#define FC1 0.9238795325112867f
#define FS1 0.3826834323650898f
#define FC2 0.7071067811865476f

// radix-16 butterfly: stage1 + inner twiddles + stage2 (in-place on v)
__device__ __forceinline__ void fft16_core(float2 v[16], float sg) {
#pragma unroll
  for (int n = 0; n < 4; n++) {
    float2 a0 = v[n], a1 = v[n+4], a2 = v[n+8], a3 = v[n+12];
    fft4(a0, a1, a2, a3, sg);
    v[n] = a0; v[n+4] = a1; v[n+8] = a2; v[n+12] = a3;
  }
  v[5]  = cmulf(v[5],  make_float2( FC1,  sg*FS1));
  v[6]  = cmulf(v[6],  make_float2( FC2,  sg*FC2));
  v[7]  = cmulf(v[7],  make_float2( FS1,  sg*FC1));
  v[9]  = cmulf(v[9],  make_float2( FC2,  sg*FC2));
  v[10] = cmuli(v[10], sg);
  v[11] = cmulf(v[11], make_float2(-FC2,  sg*FC2));
  v[13] = cmulf(v[13], make_float2( FS1,  sg*FC1));
  v[14] = cmulf(v[14], make_float2(-FC2,  sg*FC2));
  v[15] = cmulf(v[15], make_float2(-FC1, -sg*FS1));
  fft4(v[0],  v[1],  v[2],  v[3],  sg);
  fft4(v[4],  v[5],  v[6],  v[7],  sg);
  fft4(v[8],  v[9],  v[10], v[11], sg);
  fft4(v[12], v[13], v[14], v[15], sg);
}

// external twiddle + digit-reversed strided write
__device__ __forceinline__ void fft16_out(float2* __restrict__ y, float2 v[16],
                                          int s, float base, float sg) {
  float sb, cb; sincospif(base, &sb, &cb);
  float2 w1 = make_float2(cb, sg*sb);
  float s4b, c4b; sincospif(4.f * base, &s4b, &c4b);
  float2 w4 = make_float2(c4b, sg*s4b);
  float2 wrow = make_float2(1.f, 0.f);
  float2 wm = make_float2(1.f, 0.f);
#pragma unroll
  for (int m = 0; m < 16; m++) {
    int slot = ((m & 3) << 2) | (m >> 2);
    y[(size_t)m * s] = cmulf(v[slot], wm);
    if ((m & 3) == 3) { wrow = cmulf(wrow, w4); wm = wrow; }
    else               wm = cmulf(wm, w1);
  }
}

// ------------------------------ generic radix-16 pass ----------------------
__global__ void __launch_bounds__(256) k_fft16(float2* __restrict__ dst,
                                               const float2* __restrict__ src,
                                               int N, int s, int total, float sg) {
  int idx = blockIdx.x * blockDim.x + threadIdx.x;
  if (idx >= total) return;
  int per = N >> 4;
  int b = idx / per;
  int j = idx - b * per;
  int p = j / s, q = j - p * s;
  const float2* x = src + (size_t)b * N + q + (size_t)s * p;
  float2 v[16];
#pragma unroll
  for (int r = 0; r < 16; r++) v[r] = x[(size_t)r * per];
  fft16_core(v, sg);
  float2* y = dst + (size_t)b * N + q + (size_t)16 * s * p;
  float base = __int2float_rn(2 * p * s) / __int2float_rn(N);
  fft16_out(y, v, s, base, sg);
}

// ------------------------------ radix-8 pass -------------------------------
__global__ void __launch_bounds__(256) k_fft8(float2* __restrict__ dst,
                                              const float2* __restrict__ src,
                                              int N, int s, int total, float sg) {
  int idx = blockIdx.x * blockDim.x + threadIdx.x;
  if (idx >= total) return;
  int per = N >> 3;
  int b = idx / per;
  int j = idx - b * per;
  int p = j / s, q = j - p * s;
  const float2* x = src + (size_t)b * N + q + (size_t)s * p;
  float2 v[8];
#pragma unroll
  for (int r = 0; r < 8; r++) v[r] = x[(size_t)r * per];
  {
    float2 d0 = csub(v[0], v[4]);
    float2 d1 = csub(v[1], v[5]);
    float2 d2 = csub(v[2], v[6]);
    float2 d3 = csub(v[3], v[7]);
    v[0] = cadd(v[0], v[4]);
    v[1] = cadd(v[1], v[5]);
    v[2] = cadd(v[2], v[6]);
    v[3] = cadd(v[3], v[7]);
    v[4] = d0;
    v[5] = cmulf(d1, make_float2( FC2, sg*FC2));
    v[6] = cmuli(d2, sg);
    v[7] = cmulf(d3, make_float2(-FC2, sg*FC2));
  }
  fft4(v[0], v[1], v[2], v[3], sg);
  fft4(v[4], v[5], v[6], v[7], sg);
  float2* y = dst + (size_t)b * N + q + (size_t)8 * s * p;
  float base = __int2float_rn(2 * p * s) / __int2float_rn(N);
  float sb, cb; sincospif(base, &sb, &cb);
  float2 w1 = make_float2(cb, sg*sb);
  float2 wm = make_float2(1.f, 0.f);
#pragma unroll
  for (int m = 0; m < 8; m++) {
    int slot = ((m & 1) << 2) | (m >> 1);
    y[(size_t)m * s] = cmulf(v[slot], wm);
    wm = cmulf(wm, w1);
  }
}

// ------------------------------ radix-2 tail pass ---------------------------
__global__ void k_fft2(float2* __restrict__ dst, const float2* __restrict__ src,
                       int N, int nCur, int s, int total, float sign) {
  int idx = blockIdx.x * blockDim.x + threadIdx.x;
  if (idx >= total) return;
  int half = N >> 1;
  int b = idx / half;
  int j = idx - b * half;
  int p = j / s;
  int q = j - p * s;
  const float2* x = src + (size_t)b * N;
  float2*       y = dst + (size_t)b * N;
  float2 a = x[q + s*p];
  float2 c = x[q + s*p + half];
  float u = __int2float_rn(2*p) / __int2float_rn(nCur);
  float sp, cp; sincospif(u, &sp, &cp);
  float wr = cp, wi = sign * sp;
  float2 sum = make_float2(a.x + c.x, a.y + c.y);
  float dr = a.x - c.x, di = a.y - c.y;
  float2 od = make_float2(dr*wr - di*wi, dr*wi + di*wr);
  int o = q + 2*s*p;
  y[o]     = sum;
  y[o + s] = od;
}

// ------------------------------ fused first passes (forward, s=1) ----------
// Stockham s=1: thread p reads src index p + r*per, writes dst[16p + m].

// tracks: pair pp packs signals 2pp (re) and 2pp+1 (im), with input gain + zero pad
__global__ void __launch_bounds__(256) k_first_track(float2* __restrict__ dst,
                                                     const float* __restrict__ tracks) {
  int idx = blockIdx.x * blockDim.x + threadIdx.x;
  const int per = NFFT >> 4;
  if (idx >= NPAIR * per) return;
  int pp = idx / per, p = idx - pp * per;
  int sa = 2*pp, sb = 2*pp + 1;
  float ga = g_gain[sa], gb = g_gain[sb];
  const float* xa = tracks + (size_t)sa * S_LEN;
  const float* xb = tracks + (size_t)sb * S_LEN;
  float2 v[16];
#pragma unroll
  for (int r = 0; r < 16; r++) {
    int i = p + r * per;
    v[r] = (i < S_LEN) ? make_float2(ga * xa[i], gb * xb[i]) : make_float2(0.f, 0.f);
  }
  fft16_core(v, -1.f);
  float base = __int2float_rn(2 * p) / __int2float_rn(NFFT);
  fft16_out(dst + (size_t)pp * NFFT + (size_t)16 * p, v, 1, base, -1.f);
}

// master: pair b packs L (re) and R (im) of g_ms, with master input gain
__global__ void __launch_bounds__(256) k_first_master(float2* __restrict__ dst) {
  int idx = blockIdx.x * blockDim.x + threadIdx.x;
  const int per = NFFT >> 4;
  if (idx >= 2 * per) return;
  int b = idx / per, p = idx - b * per;
  float g = exp10f(g_mpd[b*26 + 0] * 0.05f);
  const float* xa = g_ms + (size_t)(b*2+0) * S_LEN;
  const float* xb = g_ms + (size_t)(b*2+1) * S_LEN;
  float2 v[16];
#pragma unroll
  for (int r = 0; r < 16; r++) {
    int i = p + r * per;
    v[r] = (i < S_LEN) ? make_float2(g * xa[i], g * xb[i]) : make_float2(0.f, 0.f);
  }
  fft16_core(v, -1.f);
  float base = __int2float_rn(2 * p) / __int2float_rn(NFFT);
  fft16_out(dst + (size_t)b * NFFT + (size_t)16 * p, v, 1, base, -1.f);
}

// wet: channel c packs fx_c (re) + ir_c (im)  [convolution-by-packing trick]
__global__ void __launch_bounds__(256) k_first_wet(float2* __restrict__ dst) {
  int idx = blockIdx.x * blockDim.x + threadIdx.x;
  const int per = NFFT >> 4;
  if (idx >= 4 * per) return;
  int c = idx / per, p = idx - c * per;
  const float* xf = g_fx + (size_t)c * S_LEN;
  const float* xi = g_ir + (size_t)c * REVN;
  float2 v[16];
#pragma unroll
  for (int r = 0; r < 16; r++) {
    int i = p + r * per;
    float a = (i < S_LEN) ? xf[i] : 0.f;
    float bi = (i < REVN) ? xi[i] : 0.f;
    v[r] = make_float2(a, bi);
  }
  fft16_core(v, -1.f);
  float base = __int2float_rn(2 * p) / __int2float_rn(NFFT);
  fft16_out(dst + (size_t)c * NFFT + (size_t)16 * p, v, 1, base, -1.f);
}

// noise: pair pp=(b*12+k12) packs ch0 (re), ch1 (im) of noise[(b,ch,k12)]
__global__ void __launch_bounds__(256) k_first_noise(float2* __restrict__ dst,
                                                     const float* __restrict__ noise) {
  int idx = blockIdx.x * blockDim.x + threadIdx.x;
  const int per = NL >> 4;
  if (idx >= 24 * per) return;
  int pp = idx / per, p = idx - pp * per;
  int b = pp / 12, k12 = pp - b * 12;
  const float* xa = noise + ((size_t)(b*2+0)*12 + k12) * NOISE_LEN;
  const float* xb = noise + ((size_t)(b*2+1)*12 + k12) * NOISE_LEN;
  float2 v[16];
#pragma unroll
  for (int r = 0; r < 16; r++) {
    int i = p + r * per;
    v[r] = (i < NOISE_LEN) ? make_float2(xa[i], xb[i]) : make_float2(0.f, 0.f);
  }
  fft16_core(v, -1.f);
  float base = __int2float_rn(2 * p) / __int2float_rn(NL);
  fft16_out(dst + (size_t)pp * NL + (size_t)16 * p, v, 1, base, -1.f);
}

// fb: pair j packs filters 2j (re), 2j+1 (im)
__global__ void __launch_bounds__(256) k_first_fb(float2* __restrict__ dst,
                                                  const float* __restrict__ fb) {
  int idx = blockIdx.x * blockDim.x + threadIdx.x;
  const int per = NL >> 4;
  if (idx >= 6 * per) return;
  int j = idx / per, p = idx - j * per;
  const float* xa = fb + (size_t)(2*j) * 1023;
  const float* xb = fb + (size_t)(2*j+1) * 1023;
  float2 v[16];
#pragma unroll
  for (int r = 0; r < 16; r++) {
    int i = p + r * per;
    v[r] = (i < 1023) ? make_float2(xa[i], xb[i]) : make_float2(0.f, 0.f);
  }
  fft16_core(v, -1.f);
  float base = __int2float_rn(2 * p) / __int2float_rn(NL);
  fft16_out(dst + (size_t)j * NL + (size_t)16 * p, v, 1, base, -1.f);
}

// ------------------------------ biquad + prep ------------------------------
__device__ void biquad_coef(int ftype, float g, float fc, float q, float* out) {
  float A  = exp10f(g * (1.f/40.f));
  float w0 = 2.f * PI_F * fc / SRATE;
  float sw, cw; sincosf(w0, &sw, &cw);
  float al = sw / (2.f * q);
  float sA = sqrtf(A);
  float b0,b1,b2,a0,a1,a2;
  if (ftype == 0) {
    b0 =  A*((A+1.f) - (A-1.f)*cw + 2.f*sA*al);
    b1 =  2.f*A*((A-1.f) - (A+1.f)*cw);
    b2 =  A*((A+1.f) - (A-1.f)*cw - 2.f*sA*al);
    a0 =  (A+1.f) + (A-1.f)*cw + 2.f*sA*al;
    a1 = -2.f*((A-1.f) + (A+1.f)*cw);
    a2 =  (A+1.f) + (A-1.f)*cw - 2.f*sA*al;
  } else if (ftype == 2) {
    b0 =  A*((A+1.f) + (A-1.f)*cw + 2.f*sA*al);
    b1 = -2.f*A*((A-1.f) + (A+1.f)*cw);
    b2 =  A*((A+1.f) + (A-1.f)*cw - 2.f*sA*al);
    a0 =  (A+1.f) - (A-1.f)*cw + 2.f*sA*al;
    a1 =  2.f*((A-1.f) - (A+1.f)*cw);
    a2 =  (A+1.f) - (A-1.f)*cw - 2.f*sA*al;
  } else {
    b0 = 1.f + al*A; b1 = -2.f*cw; b2 = 1.f - al*A;
    a0 = 1.f + al/A; a1 = -2.f*cw; a2 = 1.f - al/A;
  }
  float inv = 1.f / a0;
  out[0] = b0*inv; out[1] = b1*inv; out[2] = b2*inv;
  out[3] = 1.f;    out[4] = a1*inv; out[5] = a2*inv;
}

__global__ void k_prep(const float* __restrict__ tp, const float* __restrict__ mp) {
  int tid = threadIdx.x;
  for (int i = tid; i < NSIG*27; i += blockDim.x) {
    int j = i % 27;
    g_tpd[i] = tp[i] * (c_TR[2*j+1] - c_TR[2*j]) + c_TR[2*j];
  }
  for (int i = tid; i < 2*26; i += blockDim.x) {
    int j = i % 26;
    g_mpd[i] = mp[i] * (c_MR[2*j+1] - c_MR[2*j]) + c_MR[2*j];
  }
  __syncthreads();
  for (int i = tid; i < NSIG*6; i += blockDim.x) {
    int s = i / 6, k = i % 6;
    int ft = (k == 0) ? 0 : ((k == 5) ? 2 : 1);
    biquad_coef(ft, g_tpd[s*27+1+3*k], g_tpd[s*27+2+3*k], g_tpd[s*27+3+3*k], &g_eqT[i*6]);
  }
  for (int i = tid; i < 2*6; i += blockDim.x) {
    int s = i / 6, k = i % 6;
    int ft = (k == 0) ? 0 : ((k == 5) ? 2 : 1);
    biquad_coef(ft, g_mpd[s*26+1+3*k], g_mpd[s*26+2+3*k], g_mpd[s*26+3+3*k], &g_eqM[i*6]);
  }
  for (int s = tid; s < NSIG; s += blockDim.x) {
    g_gain[s] = exp10f(g_tpd[s*27 + 0] * 0.05f);
    g_send[s] = exp10f(g_tpd[s*27 + 25] * 0.05f);
    float theta = g_tpd[s*27 + 26] * (PI_F * 0.5f);
    g_gl[s] = sqrtf(fmaxf((PI_F*0.5f - theta) * (2.f/PI_F) * cosf(theta), 0.f));
    g_gr[s] = sqrtf(fmaxf(theta * (2.f/PI_F) * sinf(theta), 0.f));
  }
}

// ------------------------------ filter evaluation helpers ------------------
__device__ __forceinline__ float2 eval_eq6(const float* __restrict__ cf,
                                           float c1, float s1, float z2r, float z2i) {
  float hr = 1.f, hi = 0.f;
#pragma unroll
  for (int f = 0; f < 6; f++) {
    float b0 = cf[f*6+0], b1 = cf[f*6+1], b2 = cf[f*6+2];
    float a1 = cf[f*6+4], a2 = cf[f*6+5];
    float nr = b0 + b1*c1 + b2*z2r;
    float ni = -b1*s1 + b2*z2i;
    float dr = 1.f + a1*c1 + a2*z2r;
    float di = -a1*s1 + a2*z2i;
    float inv = 1.f / (dr*dr + di*di);
    float rr = (nr*dr + ni*di) * inv;
    float ri = (ni*dr - nr*di) * inv;
    float t = hr*rr - hi*ri; hi = hr*ri + hi*rr; hr = t;
  }
  return make_float2(hr, hi);
}

__device__ __forceinline__ float2 eval_smooth(float at_ms, float c1, float s1) {
  float alpha = expf(-logf(9.f) / (SRATE * at_ms * 0.001f));
  float dr = 1.f - alpha*c1;
  float di = alpha*s1;
  float inv = (1.f - alpha) / (dr*dr + di*di);
  return make_float2(dr*inv, -di*inv);
}

__device__ __forceinline__ float comp_gc(float x, float th, float ratio, float knee) {
  float ax = fabsf(x); if (ax < 1e-8f) ax = 1e-8f;
  float xdb = 20.f * log10f(ax);
  float d = xdb - th;
  if (2.f*d < -knee) return 0.f;
  if (2.f*fabsf(d) <= knee) { float e = d + 0.5f*knee; return (1.f/ratio - 1.f)*e*e/(2.f*knee); }
  return d/ratio - d;
}

// ------------------------------ paired spectral multiplies -----------------
// separate Z into (Xa, Xb), apply per-signal H, recombine conj-symmetrically
__global__ void k_eqmul_pair(float2* __restrict__ X) {
  const int nf = NFFT/2 + 1;
  int idx = blockIdx.x * blockDim.x + threadIdx.x;
  if (idx >= NPAIR * nf) return;
  int pp = idx / nf, k = idx - pp * nf;
  int m = (NFFT - k) & (NFFT - 1);
  float2* Z = X + (size_t)pp * NFFT;
  float2 Zk = Z[k], Zm = Z[m];
  float2 Xa = make_float2(0.5f*(Zk.x + Zm.x), 0.5f*(Zk.y - Zm.y));
  float2 Xb = make_float2(0.5f*(Zk.y + Zm.y), 0.5f*(Zm.x - Zk.x));
  float u = __int2float_rn(2*k) / __int2float_rn(NFFT);
  float s1, c1; sincospif(u, &s1, &c1);
  float z2r = c1*c1 - s1*s1, z2i = -2.f*c1*s1;
  float2 Ha = eval_eq6(&g_eqT[(2*pp)*36],   c1, s1, z2r, z2i);
  float2 Hb = eval_eq6(&g_eqT[(2*pp+1)*36], c1, s1, z2r, z2i);
  float2 Xa2 = cmulf(Xa, Ha), Xb2 = cmulf(Xb, Hb);
  Z[k] = make_float2(Xa2.x - Xb2.y, Xa2.y + Xb2.x);
  Z[m] = make_float2(Xa2.x + Xb2.y, Xb2.x - Xa2.y);
}

__global__ void k_compmul_pair(float2* __restrict__ X) {
  const int nf = NFFT/2 + 1;
  int idx = blockIdx.x * blockDim.x + threadIdx.x;
  if (idx >= NPAIR * nf) return;
  int pp = idx / nf, k = idx - pp * nf;
  int m = (NFFT - k) & (NFFT - 1);
  float2* Z = X + (size_t)pp * NFFT;
  float2 Zk = Z[k], Zm = Z[m];
  float2 Xa = make_float2(0.5f*(Zk.x + Zm.x), 0.5f*(Zk.y - Zm.y));
  float2 Xb = make_float2(0.5f*(Zk.y + Zm.y), 0.5f*(Zm.x - Zk.x));
  float u = __int2float_rn(2*k) / __int2float_rn(NFFT);
  float s1, c1; sincospif(u, &s1, &c1);
  float2 Ha = eval_smooth(g_tpd[(2*pp)*27 + 21],   c1, s1);
  float2 Hb = eval_smooth(g_tpd[(2*pp+1)*27 + 21], c1, s1);
  float2 Xa2 = cmulf(Xa, Ha), Xb2 = cmulf(Xb, Hb);
  Z[k] = make_float2(Xa2.x - Xb2.y, Xa2.y + Xb2.x);
  Z[m] = make_float2(Xa2.x + Xb2.y, Xb2.x - Xa2.y);
}

// master bus: L/R of a pair share the SAME filter -> direct full-range multiply
__global__ void k_eqmul_master(float2* __restrict__ X) {
  int idx = blockIdx.x * blockDim.x + threadIdx.x;
  if (idx >= 2 * NFFT) return;
  int b = idx / NFFT, k = idx - b * NFFT;
  float u = __int2float_rn(2*k) / __int2float_rn(NFFT);
  float s1, c1; sincospif(u, &s1, &c1);
  float z2r = c1*c1 - s1*s1, z2i = -2.f*c1*s1;
  float2 H = eval_eq6(&g_eqM[b*36], c1, s1, z2r, z2i);
  X[idx] = cmulf(X[idx], H);
}

__global__ void k_compmul_master(float2* __restrict__ X) {
  int idx = blockIdx.x * blockDim.x + threadIdx.x;
  if (idx >= 2 * NFFT) return;
  int b = idx / NFFT, k = idx - b * NFFT;
  float u = __int2float_rn(2*k) / __int2float_rn(NFFT);
  float s1, c1; sincospif(u, &s1, &c1);
  float2 H = eval_smooth(g_mpd[b*26 + 21], c1, s1);
  X[idx] = cmulf(X[idx], H);
}

// ------------------------------ compressor gain computers ------------------
// track: input = paired time (unnormalized); store g_x; emit packed gc
__global__ void k_compgc_track(const float2* __restrict__ src, float2* __restrict__ dst) {
  int idx = blockIdx.x * blockDim.x + threadIdx.x;
  if (idx >= NPAIR * NFFT) return;
  int pp = idx / NFFT, i = idx - pp * NFFT;
  float2 gc = make_float2(0.f, 0.f);
  if (i < S_LEN) {
    const float invN = 1.f / (float)NFFT;
    float2 t = src[idx];
    float xa = t.x * invN, xb = t.y * invN;
    g_x[(size_t)pp*S_LEN + i] = make_float2(xa, xb);
    const float* pa = &g_tpd[(2*pp)*27 + 19];
    const float* pb = &g_tpd[(2*pp+1)*27 + 19];
    gc.x = comp_gc(xa, pa[0], pa[1], pa[4]);
    gc.y = comp_gc(xb, pb[0], pb[1], pb[4]);
  }
  dst[idx] = gc;
}

__global__ void k_compgc_master(const float2* __restrict__ src, float2* __restrict__ dst) {
  int idx = blockIdx.x * blockDim.x + threadIdx.x;
  if (idx >= 2 * NFFT) return;
  int b = idx / NFFT, i = idx - b * NFFT;
  float2 gc = make_float2(0.f, 0.f);
  if (i < S_LEN) {
    const float invN = 1.f / (float)NFFT;
    float2 t = src[idx];
    float xa = t.x * invN, xb = t.y * invN;
    g_xm[(size_t)b*S_LEN + i] = make_float2(xa, xb);
    const float* pm = &g_mpd[b*26 + 19];
    gc.x = comp_gc(xa, pm[0], pm[1], pm[4]);
    gc.y = comp_gc(xb, pm[0], pm[1], pm[4]);
  }
  dst[idx] = gc;
}

// ------------------------------ pan + mix ----------------------------------
__global__ void k_applypan(const float2* __restrict__ gsb, float* __restrict__ pan) {
  int idx = blockIdx.x * blockDim.x + threadIdx.x;
  if (idx >= NPAIR * S_LEN) return;
  int pp = idx / S_LEN, i = idx - pp * S_LEN;
  const float invN = 1.f / (float)NFFT;
  int j = i + 2048; if (j > S_LEN - 1) j = S_LEN - 1;
  float2 gs = gsb[(size_t)pp*NFFT + j];
  float2 xv = g_x[(size_t)pp*S_LEN + i];
  int sa = 2*pp, sb = 2*pp + 1;
  float va = xv.x * exp10f((gs.x*invN + g_tpd[sa*27 + 24]) * 0.05f);
  float vb = xv.y * exp10f((gs.y*invN + g_tpd[sb*27 + 24]) * 0.05f);
  int ba = sa >> 4, ta = sa & 15;
  int bb = sb >> 4, tb = sb & 15;
  pan[((size_t)(ba*2+0)*16 + ta)*S_LEN + i] = va * g_gl[sa];
  pan[((size_t)(ba*2+1)*16 + ta)*S_LEN + i] = va * g_gr[sa];
  pan[((size_t)(bb*2+0)*16 + tb)*S_LEN + i] = vb * g_gl[sb];
  pan[((size_t)(bb*2+1)*16 + tb)*S_LEN + i] = vb * g_gr[sb];
}

__global__ void k_mix(const float* __restrict__ pan) {
  int idx = blockIdx.x * blockDim.x + threadIdx.x;
  if (idx >= 4 * S_LEN) return;
  int u = idx / S_LEN, i = idx - u * S_LEN;
  int b = u >> 1;
  float ms = 0.f, fs = 0.f;
#pragma unroll
  for (int t = 0; t < 16; t++) {
    float v = pan[((size_t)u*16 + t)*S_LEN + i];
    ms += v;
    fs += v * g_send[b*16 + t];
  }
  g_ms[(size_t)u*S_LEN + i] = ms;
  g_fx[(size_t)u*S_LEN + i] = fs;
}

// ------------------------------ reverb -------------------------------------
// noise pair (b,k12) spectra *= F_{k12} (same filter both channels)
__global__ void k_revmul(float2* __restrict__ Zn, const float2* __restrict__ Zf) {
  int idx = blockIdx.x * blockDim.x + threadIdx.x;
  if (idx >= 24 * NL) return;
  int pp = idx / NL, k = idx - pp * NL;
  int k12 = pp % 12;
  int j = k12 >> 1, c = k12 & 1;
  int m = (NL - k) & (NL - 1);
  float2 Fk = Zf[(size_t)j*NL + k];
  float2 Fm = Zf[(size_t)j*NL + m];
  float2 F = (c == 0)
    ? make_float2(0.5f*(Fk.x + Fm.x), 0.5f*(Fk.y - Fm.y))
    : make_float2(0.5f*(Fk.y + Fm.y), 0.5f*(Fm.x - Fk.x));
  Zn[idx] = cmulf(Zn[idx], F);
}

__global__ void k_buildir(const float2* __restrict__ Cp, const float* __restrict__ fxp) {
  int idx = blockIdx.x * blockDim.x + threadIdx.x;
  if (idx >= 4 * REVN) return;
  int u = idx / REVN, i = idx - u * REVN;
  int b = u >> 1, ch = u & 1;
  const float invnL = 1.f / (float)NL;
  float tt = (float)i * (1.f / 65535.f);
  float acc = 0.f;
#pragma unroll
  for (int k = 0; k < 12; k++) {
    float dec  = fxp[b*25 + 12 + k] * 10.f + 1.f;
    float gn   = fxp[b*25 + k];
    float2 f2  = Cp[((size_t)(b*12 + k))*NL + TAPSM1 + i];
    float filt = (ch == 0 ? f2.x : f2.y) * invnL;
    acc += filt * expf(-dec * tt) * gn;
  }
  g_ir[(size_t)u*REVN + i] = acc * (1.f / 12.f);
}

// wet product: from Z_c = FX_c + i*IR_c compute Y_c = FX_c * IR_c,
// then pack batch pairs W_b = Y_L + i*Y_R
__global__ void k_wetprod(const float2* __restrict__ Z, float2* __restrict__ W) {
  const int nf = NFFT/2 + 1;
  int idx = blockIdx.x * blockDim.x + threadIdx.x;
  if (idx >= 2 * nf) return;
  int b = idx / nf, k = idx - b * nf;
  int m = (NFFT - k) & (NFFT - 1);
  float2 Y[2];
#pragma unroll
  for (int ch = 0; ch < 2; ch++) {
    const float2* Zc = Z + (size_t)(b*2 + ch) * NFFT;
    float2 Zk = Zc[k], Zm = Zc[m];
    float2 Xf = make_float2(0.5f*(Zk.x + Zm.x), 0.5f*(Zk.y - Zm.y));
    float2 Xi = make_float2(0.5f*(Zk.y + Zm.y), 0.5f*(Zm.x - Zk.x));
    Y[ch] = cmulf(Xf, Xi);
  }
  float2* Wb = W + (size_t)b * NFFT;
  Wb[k] = make_float2(Y[0].x - Y[1].y, Y[0].y + Y[1].x);
  Wb[m] = make_float2(Y[0].x + Y[1].y, Y[1].x - Y[0].y);
}

__global__ void k_addrev(const float2* __restrict__ wet, const float* __restrict__ fxp) {
  int idx = blockIdx.x * blockDim.x + threadIdx.x;
  if (idx >= 4 * S_LEN) return;
  int u = idx / S_LEN, i = idx - u * S_LEN;
  int b = u >> 1, ch = u & 1;
  float2 w2 = wet[(size_t)b*NFFT + i];
  float w = (ch == 0 ? w2.x : w2.y) * (1.f / (float)NFFT);
  float mparam = fxp[b*25 + 24];
  g_ms[idx] += (1.f - mparam) * g_fx[idx] + mparam * w;
}

// ------------------------------ final --------------------------------------
__global__ void k_final(const float2* __restrict__ gsb, float* __restrict__ out, long long off) {
  int idx = blockIdx.x * blockDim.x + threadIdx.x;
  if (idx >= 4 * S_LEN) return;
  int u = idx / S_LEN, i = idx - u * S_LEN;
  int b = u >> 1, ch = u & 1;
  int j = i + 1024; if (j > S_LEN - 1) j = S_LEN - 1;
  float2 gs2 = gsb[(size_t)b*NFFT + j];
  float gs = (ch == 0 ? gs2.x : gs2.y) * (1.f / (float)NFFT);
  float2 xm = g_xm[(size_t)b*S_LEN + i];
  float xv = (ch == 0 ? xm.x : xm.y);
  float makeup = g_mpd[b*26 + 24];
  float og = exp10f(g_mpd[b*26 + 25] * 0.05f);
  out[off + idx] = xv * exp10f((gs + makeup) * 0.05f) * og;
}

// ------------------------------ host side ----------------------------------
static inline int grid1(long long n) { return (int)((n + 255) / 256); }

// full 5-pass runs (generic kernels) for complex data already in a buffer
static float2* fft_run_big(float2* a, float2* b, int batch, float sg) {
  float2* src = a; float2* dst = b;
  int s = 1;
  for (int i = 0; i < 4; i++) {
    int total = batch * (NFFT >> 4);
    k_fft16<<<grid1(total), 256>>>(dst, src, NFFT, s, total, sg);
    float2* t = src; src = dst; dst = t;
    s <<= 4;
  }
  {
    int total = batch * (NFFT >> 3);
    k_fft8<<<grid1(total), 256>>>(dst, src, NFFT, s, total, sg);
    float2* t = src; src = dst; dst = t;
  }
  return src;
}

// passes 2..5 after a fused first pass already wrote `cur`
static float2* fft_rest_big(float2* cur, float2* other, int batch, float sg) {
  int s = 16;
  for (int i = 0; i < 3; i++) {
    int total = batch * (NFFT >> 4);
    k_fft16<<<grid1(total), 256>>>(other, cur, NFFT, s, total, sg);
    float2* t = cur; cur = other; other = t;
    s <<= 4;
  }
  {
    int total = batch * (NFFT >> 3);
    k_fft8<<<grid1(total), 256>>>(other, cur, NFFT, s, total, sg);
    float2* t = cur; cur = other; other = t;
  }
  return cur;
}

static float2* fft_run_nl(float2* a, float2* b, int batch, float sg) {
  float2* src = a; float2* dst = b;
  int s = 1;
  for (int i = 0; i < 4; i++) {
    int total = batch * (NL >> 4);
    k_fft16<<<grid1(total), 256>>>(dst, src, NL, s, total, sg);
    float2* t = src; src = dst; dst = t;
    s <<= 4;
  }
  {
    int total = batch * (NL >> 1);
    k_fft2<<<grid1(total), 256>>>(dst, src, NL, NL / s, s, total, sg);
    float2* t = src; src = dst; dst = t;
  }
  return src;
}

static float2* fft_rest_nl(float2* cur, float2* other, int batch, float sg) {
  int s = 16;
  for (int i = 0; i < 3; i++) {
    int total = batch * (NL >> 4);
    k_fft16<<<grid1(total), 256>>>(other, cur, NL, s, total, sg);
    float2* t = cur; cur = other; other = t;
    s <<= 4;
  }
  {
    int total = batch * (NL >> 1);
    k_fft2<<<grid1(total), 256>>>(other, cur, NL, NL / s, s, total, sg);
    float2* t = cur; cur = other; other = t;
  }
  return cur;
}

extern "C" void kernel_launch(void* const* d_in, const int* in_sizes, int n_in,
                              void* d_out, int out_size) {
  const float* tracks        = (const float*)d_in[0];
  const float* track_params  = (const float*)d_in[1];
  const float* fxp           = (const float*)d_in[2];
  const float* master_params = (const float*)d_in[3];
  const float* noise         = (const float*)d_in[4];
  const float* fb            = (const float*)d_in[5];
  float* out = (float*)d_out;

  float2 *A, *B, *C, *D, *E, *F;
  float *panbuf;
  cudaGetSymbolAddress((void**)&A, g_A);
  cudaGetSymbolAddress((void**)&B, g_B);
  cudaGetSymbolAddress((void**)&C, g_C);
  cudaGetSymbolAddress((void**)&D, g_D);
  cudaGetSymbolAddress((void**)&E, g_E);
  cudaGetSymbolAddress((void**)&F, g_F);
  cudaGetSymbolAddress((void**)&panbuf, g_pan);

  long long PAN = (long long)64 * S_LEN;
  long long moff = 0;
  float* pan = panbuf;
  if ((long long)out_size >= PAN + 4LL*S_LEN) { pan = out; moff = PAN; }

  k_prep<<<1, 256>>>(track_params, master_params);

  // ---- per-track chain: gain -> EQ -> comp -> pan (16 pairs) ----
  k_first_track<<<grid1((long long)NPAIR*(NFFT>>4)), 256>>>(A, tracks);
  float2* r = fft_rest_big(A, B, NPAIR, -1.f);                      // spectrum
  k_eqmul_pair<<<grid1((long long)NPAIR*(NFFT/2+1)), 256>>>(r);
  float2* t1 = fft_run_big(r, (r == A) ? B : A, NPAIR, 1.f);        // time (xN)
  float2* t1o = (t1 == A) ? B : A;
  k_compgc_track<<<grid1((long long)NPAIR*NFFT), 256>>>(t1, t1o);   // gc packed
  float2* r2 = fft_run_big(t1o, t1, NPAIR, -1.f);
  k_compmul_pair<<<grid1((long long)NPAIR*(NFFT/2+1)), 256>>>(r2);
  float2* t2 = fft_run_big(r2, (r2 == A) ? B : A, NPAIR, 1.f);      // g_s (xN)
  k_applypan<<<grid1((long long)NPAIR*S_LEN), 256>>>(t2, pan);
  k_mix<<<grid1((long long)4*S_LEN), 256>>>(pan);

  // ---- reverb IR build (NL domain) ----
  k_first_noise<<<grid1((long long)24*(NL>>4)), 256>>>(C, noise);
  float2* rn = fft_rest_nl(C, D, 24, -1.f);
  k_first_fb<<<grid1((long long)6*(NL>>4)), 256>>>(E, fb);
  float2* rf = fft_rest_nl(E, F, 6, -1.f);
  k_revmul<<<grid1((long long)24*NL), 256>>>(rn, rf);
  float2* ri = fft_run_nl(rn, (rn == C) ? D : C, 24, 1.f);
  k_buildir<<<grid1((long long)4*REVN), 256>>>(ri, fxp);

  // ---- wet convolution: FFT(fx_c + i*ir_c), product, paired inverse ----
  k_first_wet<<<grid1((long long)4*(NFFT>>4)), 256>>>(A);
  float2* rw = fft_rest_big(A, B, 4, -1.f);
  float2* rwo = (rw == A) ? B : A;
  k_wetprod<<<grid1((long long)2*(NFFT/2+1)), 256>>>(rw, rwo);
  float2* tw = fft_run_big(rwo, rw, 2, 1.f);                        // wet time (xN)
  k_addrev<<<grid1((long long)4*S_LEN), 256>>>(tw, fxp);

  // ---- master chain: gain -> EQ -> comp -> gain (2 pairs, shared filters) --
  k_first_master<<<grid1((long long)2*(NFFT>>4)), 256>>>(A);
  float2* m1 = fft_rest_big(A, B, 2, -1.f);
  k_eqmul_master<<<grid1((long long)2*NFFT), 256>>>(m1);
  float2* mt1 = fft_run_big(m1, (m1 == A) ? B : A, 2, 1.f);
  float2* mt1o = (mt1 == A) ? B : A;
  k_compgc_master<<<grid1((long long)2*NFFT), 256>>>(mt1, mt1o);
  float2* m2 = fft_run_big(mt1o, mt1, 2, -1.f);
  k_compmul_master<<<grid1((long long)2*NFFT), 256>>>(m2);
  float2* mt2 = fft_run_big(m2, (m2 == A) ? B : A, 2, 1.f);
  k_final<<<grid1((long long)4*S_LEN), 256>>>(mt2, out, moff);
}

// round 5
// speedup vs baseline: 1.9944x; 1.0014x over previous
#include <cuda_runtime.h>
#include <cstdint>

// ---------------------------------------------------------------------------
// AdvancedMixConsole: paired-real radix-16 Stockham FFT mixing console
// Two real signals packed per complex FFT everywhere.
// ---------------------------------------------------------------------------

#define SRATE    44100.0f
#define S_LEN    262144
#define NFFT     524288
#define NL       131072
#define REVN     65536
#define NOISE_LEN 66558
#define TAPSM1   1022
#define NSIG     32          // BS*NT
#define NPAIR    16
#define PI_F     3.14159265358979323846f

// ------------------------------ scratch (static device, no allocation) -----
__device__ float2 g_A[(size_t)NPAIR * NFFT];   // 67 MB
__device__ float2 g_B[(size_t)NPAIR * NFFT];   // 67 MB
__device__ float2 g_C[(size_t)24 * NL];        // 25 MB  (noise pairs)
__device__ float2 g_D[(size_t)24 * NL];        // 25 MB
__device__ float2 g_E[(size_t)6 * NL];         // 6.3 MB (fb pairs)
__device__ float2 g_F[(size_t)6 * NL];         // 6.3 MB
__device__ float2 g_x[(size_t)NPAIR * S_LEN];  // 33.5 MB paired post-EQ time
__device__ float2 g_xm[(size_t)2 * S_LEN];     // master post-EQ time (paired L/R)
__device__ float  g_pan[(size_t)64 * S_LEN];   // fallback pan buffer
__device__ float  g_ms[(size_t)4 * S_LEN];     // master bus (BS,2,SEQ)
__device__ float  g_fx[(size_t)4 * S_LEN];     // fx send bus
__device__ float  g_ir[(size_t)4 * REVN];      // reverb IR
__device__ float  g_tpd[NSIG * 27];
__device__ float  g_mpd[2 * 26];
__device__ float  g_eqT[NSIG * 36];
__device__ float  g_eqM[2 * 36];
__device__ float  g_gain[NSIG];                // input gain (linear)
__device__ float  g_send[NSIG];                // send gain (linear)
__device__ float  g_gl[NSIG];                  // pan left gain
__device__ float  g_gr[NSIG];                  // pan right gain

// ------------------------------ parameter ranges ---------------------------
__constant__ float c_TR[54] = {
  -48.f,48.f,
  -12.f,12.f, 20.f,2000.f, 0.1f,5.f,
  -12.f,12.f, 80.f,2000.f, 0.1f,5.f,
  -12.f,12.f, 2000.f,8000.f, 0.1f,5.f,
  -12.f,12.f, 8000.f,12000.f, 0.1f,5.f,
  -12.f,12.f, 12000.f,21050.f, 0.1f,5.f,
  -12.f,12.f, 6000.f,21050.f, 0.1f,5.f,
  -60.f,0.f, 1.f,10.f, 5.f,250.f, 10.f,250.f, 3.f,12.f, 0.f,6.f,
  -80.f,12.f, 0.f,1.f
};
__constant__ float c_MR[52] = {
  -48.f,48.f,
  -12.f,12.f, 20.f,2000.f, 0.1f,5.f,
  -12.f,12.f, 80.f,2000.f, 0.1f,5.f,
  -12.f,12.f, 2000.f,8000.f, 0.1f,5.f,
  -12.f,12.f, 8000.f,12000.f, 0.1f,5.f,
  -12.f,12.f, 12000.f,21050.f, 0.1f,5.f,
  -12.f,12.f, 6000.f,21050.f, 0.1f,5.f,
  -60.f,0.f, 1.f,10.f, 5.f,250.f, 10.f,250.f, 3.f,12.f, 0.f,6.f,
  -48.f,48.f
};

__device__ __forceinline__ float2 cadd(float2 a, float2 b) { return make_float2(a.x+b.x, a.y+b.y); }
__device__ __forceinline__ float2 csub(float2 a, float2 b) { return make_float2(a.x-b.x, a.y-b.y); }
__device__ __forceinline__ float2 cmulf(float2 a, float2 b) {
  return make_float2(a.x*b.x - a.y*b.y, a.x*b.y + a.y*b.x);
}
__device__ __forceinline__ float2 cmuli(float2 a, float sg) { return make_float2(-sg*a.y, sg*a.x); }

__device__ __forceinline__ void fft4(float2& x0, float2& x1, float2& x2, float2& x3, float sg) {
  float2 t0 = cadd(x0, x2), t1 = csub(x0, x2);
  float2 t2 = cadd(x1, x3), t3 = cmuli(csub(x1, x3), sg);
  x0 = cadd(t0, t2); x2 = csub(t0, t2);
  x1 = cadd(t1, t3); x3 = csub(t1, t3);
}

#define FC1 0.9238795325112867f
#define FS1 0.3826834323650898f
#define FC2 0.7071067811865476f

// radix-16 butterfly: stage1 + inner twiddles + stage2 (in-place on v)
__device__ __forceinline__ void fft16_core(float2 v[16], float sg) {
#pragma unroll
  for (int n = 0; n < 4; n++) {
    float2 a0 = v[n], a1 = v[n+4], a2 = v[n+8], a3 = v[n+12];
    fft4(a0, a1, a2, a3, sg);
    v[n] = a0; v[n+4] = a1; v[n+8] = a2; v[n+12] = a3;
  }
  v[5]  = cmulf(v[5],  make_float2( FC1,  sg*FS1));
  v[6]  = cmulf(v[6],  make_float2( FC2,  sg*FC2));
  v[7]  = cmulf(v[7],  make_float2( FS1,  sg*FC1));
  v[9]  = cmulf(v[9],  make_float2( FC2,  sg*FC2));
  v[10] = cmuli(v[10], sg);
  v[11] = cmulf(v[11], make_float2(-FC2,  sg*FC2));
  v[13] = cmulf(v[13], make_float2( FS1,  sg*FC1));
  v[14] = cmulf(v[14], make_float2(-FC2,  sg*FC2));
  v[15] = cmulf(v[15], make_float2(-FC1, -sg*FS1));
  fft4(v[0],  v[1],  v[2],  v[3],  sg);
  fft4(v[4],  v[5],  v[6],  v[7],  sg);
  fft4(v[8],  v[9],  v[10], v[11], sg);
  fft4(v[12], v[13], v[14], v[15], sg);
}

// external twiddle + digit-reversed strided write
__device__ __forceinline__ void fft16_out(float2* __restrict__ y, float2 v[16],
                                          int s, float base, float sg) {
  float sb, cb; sincospif(base, &sb, &cb);
  float2 w1 = make_float2(cb, sg*sb);
  float s4b, c4b; sincospif(4.f * base, &s4b, &c4b);
  float2 w4 = make_float2(c4b, sg*s4b);
  float2 wrow = make_float2(1.f, 0.f);
  float2 wm = make_float2(1.f, 0.f);
#pragma unroll
  for (int m = 0; m < 16; m++) {
    int slot = ((m & 3) << 2) | (m >> 2);
    y[(size_t)m * s] = cmulf(v[slot], wm);
    if ((m & 3) == 3) { wrow = cmulf(wrow, w4); wm = wrow; }
    else               wm = cmulf(wm, w1);
  }
}

// ------------------------------ generic radix-16 pass ----------------------
__global__ void __launch_bounds__(256) k_fft16(float2* __restrict__ dst,
                                               const float2* __restrict__ src,
                                               int N, int s, int total, float sg) {
  int idx = blockIdx.x * blockDim.x + threadIdx.x;
  if (idx >= total) return;
  int per = N >> 4;
  int b = idx / per;
  int j = idx - b * per;
  int p = j / s, q = j - p * s;
  const float2* x = src + (size_t)b * N + q + (size_t)s * p;
  float2 v[16];
#pragma unroll
  for (int r = 0; r < 16; r++) v[r] = x[(size_t)r * per];
  fft16_core(v, sg);
  float2* y = dst + (size_t)b * N + q + (size_t)16 * s * p;
  float base = __int2float_rn(2 * p * s) / __int2float_rn(N);
  fft16_out(y, v, s, base, sg);
}

// ------------------------------ radix-8 pass -------------------------------
__global__ void __launch_bounds__(256) k_fft8(float2* __restrict__ dst,
                                              const float2* __restrict__ src,
                                              int N, int s, int total, float sg) {
  int idx = blockIdx.x * blockDim.x + threadIdx.x;
  if (idx >= total) return;
  int per = N >> 3;
  int b = idx / per;
  int j = idx - b * per;
  int p = j / s, q = j - p * s;
  const float2* x = src + (size_t)b * N + q + (size_t)s * p;
  float2 v[8];
#pragma unroll
  for (int r = 0; r < 8; r++) v[r] = x[(size_t)r * per];
  {
    float2 d0 = csub(v[0], v[4]);
    float2 d1 = csub(v[1], v[5]);
    float2 d2 = csub(v[2], v[6]);
    float2 d3 = csub(v[3], v[7]);
    v[0] = cadd(v[0], v[4]);
    v[1] = cadd(v[1], v[5]);
    v[2] = cadd(v[2], v[6]);
    v[3] = cadd(v[3], v[7]);
    v[4] = d0;
    v[5] = cmulf(d1, make_float2( FC2, sg*FC2));
    v[6] = cmuli(d2, sg);
    v[7] = cmulf(d3, make_float2(-FC2, sg*FC2));
  }
  fft4(v[0], v[1], v[2], v[3], sg);
  fft4(v[4], v[5], v[6], v[7], sg);
  float2* y = dst + (size_t)b * N + q + (size_t)8 * s * p;
  float base = __int2float_rn(2 * p * s) / __int2float_rn(N);
  float sb, cb; sincospif(base, &sb, &cb);
  float2 w1 = make_float2(cb, sg*sb);
  float2 wm = make_float2(1.f, 0.f);
#pragma unroll
  for (int m = 0; m < 8; m++) {
    int slot = ((m & 1) << 2) | (m >> 1);
    y[(size_t)m * s] = cmulf(v[slot], wm);
    wm = cmulf(wm, w1);
  }
}

// ------------------------------ radix-2 tail pass ---------------------------
__global__ void k_fft2(float2* __restrict__ dst, const float2* __restrict__ src,
                       int N, int nCur, int s, int total, float sign) {
  int idx = blockIdx.x * blockDim.x + threadIdx.x;
  if (idx >= total) return;
  int half = N >> 1;
  int b = idx / half;
  int j = idx - b * half;
  int p = j / s;
  int q = j - p * s;
  const float2* x = src + (size_t)b * N;
  float2*       y = dst + (size_t)b * N;
  float2 a = x[q + s*p];
  float2 c = x[q + s*p + half];
  float u = __int2float_rn(2*p) / __int2float_rn(nCur);
  float sp, cp; sincospif(u, &sp, &cp);
  float wr = cp, wi = sign * sp;
  float2 sum = make_float2(a.x + c.x, a.y + c.y);
  float dr = a.x - c.x, di = a.y - c.y;
  float2 od = make_float2(dr*wr - di*wi, dr*wi + di*wr);
  int o = q + 2*s*p;
  y[o]     = sum;
  y[o + s] = od;
}

// ------------------------------ fused first passes (forward, s=1) ----------
// Stockham s=1: thread p reads src index p + r*per, writes dst[16p + m].

// tracks: pair pp packs signals 2pp (re) and 2pp+1 (im), with input gain + zero pad
__global__ void __launch_bounds__(256) k_first_track(float2* __restrict__ dst,
                                                     const float* __restrict__ tracks) {
  int idx = blockIdx.x * blockDim.x + threadIdx.x;
  const int per = NFFT >> 4;
  if (idx >= NPAIR * per) return;
  int pp = idx / per, p = idx - pp * per;
  int sa = 2*pp, sb = 2*pp + 1;
  float ga = g_gain[sa], gb = g_gain[sb];
  const float* xa = tracks + (size_t)sa * S_LEN;
  const float* xb = tracks + (size_t)sb * S_LEN;
  float2 v[16];
#pragma unroll
  for (int r = 0; r < 16; r++) {
    int i = p + r * per;
    v[r] = (i < S_LEN) ? make_float2(ga * xa[i], gb * xb[i]) : make_float2(0.f, 0.f);
  }
  fft16_core(v, -1.f);
  float base = __int2float_rn(2 * p) / __int2float_rn(NFFT);
  fft16_out(dst + (size_t)pp * NFFT + (size_t)16 * p, v, 1, base, -1.f);
}

// master: pair b packs L (re) and R (im) of g_ms, with master input gain
__global__ void __launch_bounds__(256) k_first_master(float2* __restrict__ dst) {
  int idx = blockIdx.x * blockDim.x + threadIdx.x;
  const int per = NFFT >> 4;
  if (idx >= 2 * per) return;
  int b = idx / per, p = idx - b * per;
  float g = exp10f(g_mpd[b*26 + 0] * 0.05f);
  const float* xa = g_ms + (size_t)(b*2+0) * S_LEN;
  const float* xb = g_ms + (size_t)(b*2+1) * S_LEN;
  float2 v[16];
#pragma unroll
  for (int r = 0; r < 16; r++) {
    int i = p + r * per;
    v[r] = (i < S_LEN) ? make_float2(g * xa[i], g * xb[i]) : make_float2(0.f, 0.f);
  }
  fft16_core(v, -1.f);
  float base = __int2float_rn(2 * p) / __int2float_rn(NFFT);
  fft16_out(dst + (size_t)b * NFFT + (size_t)16 * p, v, 1, base, -1.f);
}

// wet: channel c packs fx_c (re) + ir_c (im)  [convolution-by-packing trick]
__global__ void __launch_bounds__(256) k_first_wet(float2* __restrict__ dst) {
  int idx = blockIdx.x * blockDim.x + threadIdx.x;
  const int per = NFFT >> 4;
  if (idx >= 4 * per) return;
  int c = idx / per, p = idx - c * per;
  const float* xf = g_fx + (size_t)c * S_LEN;
  const float* xi = g_ir + (size_t)c * REVN;
  float2 v[16];
#pragma unroll
  for (int r = 0; r < 16; r++) {
    int i = p + r * per;
    float a = (i < S_LEN) ? xf[i] : 0.f;
    float bi = (i < REVN) ? xi[i] : 0.f;
    v[r] = make_float2(a, bi);
  }
  fft16_core(v, -1.f);
  float base = __int2float_rn(2 * p) / __int2float_rn(NFFT);
  fft16_out(dst + (size_t)c * NFFT + (size_t)16 * p, v, 1, base, -1.f);
}

// noise: pair pp=(b*12+k12) packs ch0 (re), ch1 (im) of noise[(b,ch,k12)]
__global__ void __launch_bounds__(256) k_first_noise(float2* __restrict__ dst,
                                                     const float* __restrict__ noise) {
  int idx = blockIdx.x * blockDim.x + threadIdx.x;
  const int per = NL >> 4;
  if (idx >= 24 * per) return;
  int pp = idx / per, p = idx - pp * per;
  int b = pp / 12, k12 = pp - b * 12;
  const float* xa = noise + ((size_t)(b*2+0)*12 + k12) * NOISE_LEN;
  const float* xb = noise + ((size_t)(b*2+1)*12 + k12) * NOISE_LEN;
  float2 v[16];
#pragma unroll
  for (int r = 0; r < 16; r++) {
    int i = p + r * per;
    v[r] = (i < NOISE_LEN) ? make_float2(xa[i], xb[i]) : make_float2(0.f, 0.f);
  }
  fft16_core(v, -1.f);
  float base = __int2float_rn(2 * p) / __int2float_rn(NL);
  fft16_out(dst + (size_t)pp * NL + (size_t)16 * p, v, 1, base, -1.f);
}

// fb: pair j packs filters 2j (re), 2j+1 (im)
__global__ void __launch_bounds__(256) k_first_fb(float2* __restrict__ dst,
                                                  const float* __restrict__ fb) {
  int idx = blockIdx.x * blockDim.x + threadIdx.x;
  const int per = NL >> 4;
  if (idx >= 6 * per) return;
  int j = idx / per, p = idx - j * per;
  const float* xa = fb + (size_t)(2*j) * 1023;
  const float* xb = fb + (size_t)(2*j+1) * 1023;
  float2 v[16];
#pragma unroll
  for (int r = 0; r < 16; r++) {
    int i = p + r * per;
    v[r] = (i < 1023) ? make_float2(xa[i], xb[i]) : make_float2(0.f, 0.f);
  }
  fft16_core(v, -1.f);
  float base = __int2float_rn(2 * p) / __int2float_rn(NL);
  fft16_out(dst + (size_t)j * NL + (size_t)16 * p, v, 1, base, -1.f);
}

// ------------------------------ biquad + prep ------------------------------
__device__ void biquad_coef(int ftype, float g, float fc, float q, float* out) {
  float A  = exp10f(g * (1.f/40.f));
  float w0 = 2.f * PI_F * fc / SRATE;
  float sw, cw; sincosf(w0, &sw, &cw);
  float al = sw / (2.f * q);
  float sA = sqrtf(A);
  float b0,b1,b2,a0,a1,a2;
  if (ftype == 0) {
    b0 =  A*((A+1.f) - (A-1.f)*cw + 2.f*sA*al);
    b1 =  2.f*A*((A-1.f) - (A+1.f)*cw);
    b2 =  A*((A+1.f) - (A-1.f)*cw - 2.f*sA*al);
    a0 =  (A+1.f) + (A-1.f)*cw + 2.f*sA*al;
    a1 = -2.f*((A-1.f) + (A+1.f)*cw);
    a2 =  (A+1.f) + (A-1.f)*cw - 2.f*sA*al;
  } else if (ftype == 2) {
    b0 =  A*((A+1.f) + (A-1.f)*cw + 2.f*sA*al);
    b1 = -2.f*A*((A-1.f) + (A+1.f)*cw);
    b2 =  A*((A+1.f) + (A-1.f)*cw - 2.f*sA*al);
    a0 =  (A+1.f) - (A-1.f)*cw + 2.f*sA*al;
    a1 =  2.f*((A-1.f) - (A+1.f)*cw);
    a2 =  (A+1.f) - (A-1.f)*cw - 2.f*sA*al;
  } else {
    b0 = 1.f + al*A; b1 = -2.f*cw; b2 = 1.f - al*A;
    a0 = 1.f + al/A; a1 = -2.f*cw; a2 = 1.f - al/A;
  }
  float inv = 1.f / a0;
  out[0] = b0*inv; out[1] = b1*inv; out[2] = b2*inv;
  out[3] = 1.f;    out[4] = a1*inv; out[5] = a2*inv;
}

__global__ void k_prep(const float* __restrict__ tp, const float* __restrict__ mp) {
  int tid = threadIdx.x;
  for (int i = tid; i < NSIG*27; i += blockDim.x) {
    int j = i % 27;
    g_tpd[i] = tp[i] * (c_TR[2*j+1] - c_TR[2*j]) + c_TR[2*j];
  }
  for (int i = tid; i < 2*26; i += blockDim.x) {
    int j = i % 26;
    g_mpd[i] = mp[i] * (c_MR[2*j+1] - c_MR[2*j]) + c_MR[2*j];
  }
  __syncthreads();
  for (int i = tid; i < NSIG*6; i += blockDim.x) {
    int s = i / 6, k = i % 6;
    int ft = (k == 0) ? 0 : ((k == 5) ? 2 : 1);
    biquad_coef(ft, g_tpd[s*27+1+3*k], g_tpd[s*27+2+3*k], g_tpd[s*27+3+3*k], &g_eqT[i*6]);
  }
  for (int i = tid; i < 2*6; i += blockDim.x) {
    int s = i / 6, k = i % 6;
    int ft = (k == 0) ? 0 : ((k == 5) ? 2 : 1);
    biquad_coef(ft, g_mpd[s*26+1+3*k], g_mpd[s*26+2+3*k], g_mpd[s*26+3+3*k], &g_eqM[i*6]);
  }
  for (int s = tid; s < NSIG; s += blockDim.x) {
    g_gain[s] = exp10f(g_tpd[s*27 + 0] * 0.05f);
    g_send[s] = exp10f(g_tpd[s*27 + 25] * 0.05f);
    float theta = g_tpd[s*27 + 26] * (PI_F * 0.5f);
    g_gl[s] = sqrtf(fmaxf((PI_F*0.5f - theta) * (2.f/PI_F) * cosf(theta), 0.f));
    g_gr[s] = sqrtf(fmaxf(theta * (2.f/PI_F) * sinf(theta), 0.f));
  }
}

// ------------------------------ filter evaluation helpers ------------------
__device__ __forceinline__ float2 eval_eq6(const float* __restrict__ cf,
                                           float c1, float s1, float z2r, float z2i) {
  float hr = 1.f, hi = 0.f;
#pragma unroll
  for (int f = 0; f < 6; f++) {
    float b0 = cf[f*6+0], b1 = cf[f*6+1], b2 = cf[f*6+2];
    float a1 = cf[f*6+4], a2 = cf[f*6+5];
    float nr = b0 + b1*c1 + b2*z2r;
    float ni = -b1*s1 + b2*z2i;
    float dr = 1.f + a1*c1 + a2*z2r;
    float di = -a1*s1 + a2*z2i;
    float inv = 1.f / (dr*dr + di*di);
    float rr = (nr*dr + ni*di) * inv;
    float ri = (ni*dr - nr*di) * inv;
    float t = hr*rr - hi*ri; hi = hr*ri + hi*rr; hr = t;
  }
  return make_float2(hr, hi);
}

__device__ __forceinline__ float2 eval_smooth(float at_ms, float c1, float s1) {
  float alpha = expf(-logf(9.f) / (SRATE * at_ms * 0.001f));
  float dr = 1.f - alpha*c1;
  float di = alpha*s1;
  float inv = (1.f - alpha) / (dr*dr + di*di);
  return make_float2(dr*inv, -di*inv);
}

__device__ __forceinline__ float comp_gc(float x, float th, float ratio, float knee) {
  float ax = fabsf(x); if (ax < 1e-8f) ax = 1e-8f;
  float xdb = 20.f * log10f(ax);
  float d = xdb - th;
  if (2.f*d < -knee) return 0.f;
  if (2.f*fabsf(d) <= knee) { float e = d + 0.5f*knee; return (1.f/ratio - 1.f)*e*e/(2.f*knee); }
  return d/ratio - d;
}

// ------------------------------ paired spectral multiplies -----------------
// separate Z into (Xa, Xb), apply per-signal H, recombine conj-symmetrically
__global__ void k_eqmul_pair(float2* __restrict__ X) {
  const int nf = NFFT/2 + 1;
  int idx = blockIdx.x * blockDim.x + threadIdx.x;
  if (idx >= NPAIR * nf) return;
  int pp = idx / nf, k = idx - pp * nf;
  int m = (NFFT - k) & (NFFT - 1);
  float2* Z = X + (size_t)pp * NFFT;
  float2 Zk = Z[k], Zm = Z[m];
  float2 Xa = make_float2(0.5f*(Zk.x + Zm.x), 0.5f*(Zk.y - Zm.y));
  float2 Xb = make_float2(0.5f*(Zk.y + Zm.y), 0.5f*(Zm.x - Zk.x));
  float u = __int2float_rn(2*k) / __int2float_rn(NFFT);
  float s1, c1; sincospif(u, &s1, &c1);
  float z2r = c1*c1 - s1*s1, z2i = -2.f*c1*s1;
  float2 Ha = eval_eq6(&g_eqT[(2*pp)*36],   c1, s1, z2r, z2i);
  float2 Hb = eval_eq6(&g_eqT[(2*pp+1)*36], c1, s1, z2r, z2i);
  float2 Xa2 = cmulf(Xa, Ha), Xb2 = cmulf(Xb, Hb);
  Z[k] = make_float2(Xa2.x - Xb2.y, Xa2.y + Xb2.x);
  Z[m] = make_float2(Xa2.x + Xb2.y, Xb2.x - Xa2.y);
}

__global__ void k_compmul_pair(float2* __restrict__ X) {
  const int nf = NFFT/2 + 1;
  int idx = blockIdx.x * blockDim.x + threadIdx.x;
  if (idx >= NPAIR * nf) return;
  int pp = idx / nf, k = idx - pp * nf;
  int m = (NFFT - k) & (NFFT - 1);
  float2* Z = X + (size_t)pp * NFFT;
  float2 Zk = Z[k], Zm = Z[m];
  float2 Xa = make_float2(0.5f*(Zk.x + Zm.x), 0.5f*(Zk.y - Zm.y));
  float2 Xb = make_float2(0.5f*(Zk.y + Zm.y), 0.5f*(Zm.x - Zk.x));
  float u = __int2float_rn(2*k) / __int2float_rn(NFFT);
  float s1, c1; sincospif(u, &s1, &c1);
  float2 Ha = eval_smooth(g_tpd[(2*pp)*27 + 21],   c1, s1);
  float2 Hb = eval_smooth(g_tpd[(2*pp+1)*27 + 21], c1, s1);
  float2 Xa2 = cmulf(Xa, Ha), Xb2 = cmulf(Xb, Hb);
  Z[k] = make_float2(Xa2.x - Xb2.y, Xa2.y + Xb2.x);
  Z[m] = make_float2(Xa2.x + Xb2.y, Xb2.x - Xa2.y);
}

// master bus: L/R of a pair share the SAME filter -> direct full-range multiply
__global__ void k_eqmul_master(float2* __restrict__ X) {
  int idx = blockIdx.x * blockDim.x + threadIdx.x;
  if (idx >= 2 * NFFT) return;
  int b = idx / NFFT, k = idx - b * NFFT;
  float u = __int2float_rn(2*k) / __int2float_rn(NFFT);
  float s1, c1; sincospif(u, &s1, &c1);
  float z2r = c1*c1 - s1*s1, z2i = -2.f*c1*s1;
  float2 H = eval_eq6(&g_eqM[b*36], c1, s1, z2r, z2i);
  X[idx] = cmulf(X[idx], H);
}

__global__ void k_compmul_master(float2* __restrict__ X) {
  int idx = blockIdx.x * blockDim.x + threadIdx.x;
  if (idx >= 2 * NFFT) return;
  int b = idx / NFFT, k = idx - b * NFFT;
  float u = __int2float_rn(2*k) / __int2float_rn(NFFT);
  float s1, c1; sincospif(u, &s1, &c1);
  float2 H = eval_smooth(g_mpd[b*26 + 21], c1, s1);
  X[idx] = cmulf(X[idx], H);
}

// ------------------------------ compressor gain computers ------------------
// track: input = paired time (unnormalized); store g_x; emit packed gc
__global__ void k_compgc_track(const float2* __restrict__ src, float2* __restrict__ dst) {
  int idx = blockIdx.x * blockDim.x + threadIdx.x;
  if (idx >= NPAIR * NFFT) return;
  int pp = idx / NFFT, i = idx - pp * NFFT;
  float2 gc = make_float2(0.f, 0.f);
  if (i < S_LEN) {
    const float invN = 1.f / (float)NFFT;
    float2 t = src[idx];
    float xa = t.x * invN, xb = t.y * invN;
    g_x[(size_t)pp*S_LEN + i] = make_float2(xa, xb);
    const float* pa = &g_tpd[(2*pp)*27 + 19];
    const float* pb = &g_tpd[(2*pp+1)*27 + 19];
    gc.x = comp_gc(xa, pa[0], pa[1], pa[4]);
    gc.y = comp_gc(xb, pb[0], pb[1], pb[4]);
  }
  dst[idx] = gc;
}

__global__ void k_compgc_master(const float2* __restrict__ src, float2* __restrict__ dst) {
  int idx = blockIdx.x * blockDim.x + threadIdx.x;
  if (idx >= 2 * NFFT) return;
  int b = idx / NFFT, i = idx - b * NFFT;
  float2 gc = make_float2(0.f, 0.f);
  if (i < S_LEN) {
    const float invN = 1.f / (float)NFFT;
    float2 t = src[idx];
    float xa = t.x * invN, xb = t.y * invN;
    g_xm[(size_t)b*S_LEN + i] = make_float2(xa, xb);
    const float* pm = &g_mpd[b*26 + 19];
    gc.x = comp_gc(xa, pm[0], pm[1], pm[4]);
    gc.y = comp_gc(xb, pm[0], pm[1], pm[4]);
  }
  dst[idx] = gc;
}

// ------------------------------ pan + mix ----------------------------------
__global__ void k_applypan(const float2* __restrict__ gsb, float* __restrict__ pan) {
  int idx = blockIdx.x * blockDim.x + threadIdx.x;
  if (idx >= NPAIR * S_LEN) return;
  int pp = idx / S_LEN, i = idx - pp * S_LEN;
  const float invN = 1.f / (float)NFFT;
  int j = i + 2048; if (j > S_LEN - 1) j = S_LEN - 1;
  float2 gs = gsb[(size_t)pp*NFFT + j];
  float2 xv = g_x[(size_t)pp*S_LEN + i];
  int sa = 2*pp, sb = 2*pp + 1;
  float va = xv.x * exp10f((gs.x*invN + g_tpd[sa*27 + 24]) * 0.05f);
  float vb = xv.y * exp10f((gs.y*invN + g_tpd[sb*27 + 24]) * 0.05f);
  int ba = sa >> 4, ta = sa & 15;
  int bb = sb >> 4, tb = sb & 15;
  pan[((size_t)(ba*2+0)*16 + ta)*S_LEN + i] = va * g_gl[sa];
  pan[((size_t)(ba*2+1)*16 + ta)*S_LEN + i] = va * g_gr[sa];
  pan[((size_t)(bb*2+0)*16 + tb)*S_LEN + i] = vb * g_gl[sb];
  pan[((size_t)(bb*2+1)*16 + tb)*S_LEN + i] = vb * g_gr[sb];
}

__global__ void k_mix(const float* __restrict__ pan) {
  int idx = blockIdx.x * blockDim.x + threadIdx.x;
  if (idx >= 4 * S_LEN) return;
  int u = idx / S_LEN, i = idx - u * S_LEN;
  int b = u >> 1;
  float ms = 0.f, fs = 0.f;
#pragma unroll
  for (int t = 0; t < 16; t++) {
    float v = pan[((size_t)u*16 + t)*S_LEN + i];
    ms += v;
    fs += v * g_send[b*16 + t];
  }
  g_ms[(size_t)u*S_LEN + i] = ms;
  g_fx[(size_t)u*S_LEN + i] = fs;
}

// ------------------------------ reverb -------------------------------------
// noise pair (b,k12) spectra *= F_{k12} (same filter both channels)
__global__ void k_revmul(float2* __restrict__ Zn, const float2* __restrict__ Zf) {
  int idx = blockIdx.x * blockDim.x + threadIdx.x;
  if (idx >= 24 * NL) return;
  int pp = idx / NL, k = idx - pp * NL;
  int k12 = pp % 12;
  int j = k12 >> 1, c = k12 & 1;
  int m = (NL - k) & (NL - 1);
  float2 Fk = Zf[(size_t)j*NL + k];
  float2 Fm = Zf[(size_t)j*NL + m];
  float2 F = (c == 0)
    ? make_float2(0.5f*(Fk.x + Fm.x), 0.5f*(Fk.y - Fm.y))
    : make_float2(0.5f*(Fk.y + Fm.y), 0.5f*(Fm.x - Fk.x));
  Zn[idx] = cmulf(Zn[idx], F);
}

__global__ void k_buildir(const float2* __restrict__ Cp, const float* __restrict__ fxp) {
  int idx = blockIdx.x * blockDim.x + threadIdx.x;
  if (idx >= 4 * REVN) return;
  int u = idx / REVN, i = idx - u * REVN;
  int b = u >> 1, ch = u & 1;
  const float invnL = 1.f / (float)NL;
  float tt = (float)i * (1.f / 65535.f);
  float acc = 0.f;
#pragma unroll
  for (int k = 0; k < 12; k++) {
    float dec  = fxp[b*25 + 12 + k] * 10.f + 1.f;
    float gn   = fxp[b*25 + k];
    float2 f2  = Cp[((size_t)(b*12 + k))*NL + TAPSM1 + i];
    float filt = (ch == 0 ? f2.x : f2.y) * invnL;
    acc += filt * expf(-dec * tt) * gn;
  }
  g_ir[(size_t)u*REVN + i] = acc * (1.f / 12.f);
}

// wet product: from Z_c = FX_c + i*IR_c compute Y_c = FX_c * IR_c,
// then pack batch pairs W_b = Y_L + i*Y_R
__global__ void k_wetprod(const float2* __restrict__ Z, float2* __restrict__ W) {
  const int nf = NFFT/2 + 1;
  int idx = blockIdx.x * blockDim.x + threadIdx.x;
  if (idx >= 2 * nf) return;
  int b = idx / nf, k = idx - b * nf;
  int m = (NFFT - k) & (NFFT - 1);
  float2 Y[2];
#pragma unroll
  for (int ch = 0; ch < 2; ch++) {
    const float2* Zc = Z + (size_t)(b*2 + ch) * NFFT;
    float2 Zk = Zc[k], Zm = Zc[m];
    float2 Xf = make_float2(0.5f*(Zk.x + Zm.x), 0.5f*(Zk.y - Zm.y));
    float2 Xi = make_float2(0.5f*(Zk.y + Zm.y), 0.5f*(Zm.x - Zk.x));
    Y[ch] = cmulf(Xf, Xi);
  }
  float2* Wb = W + (size_t)b * NFFT;
  Wb[k] = make_float2(Y[0].x - Y[1].y, Y[0].y + Y[1].x);
  Wb[m] = make_float2(Y[0].x + Y[1].y, Y[1].x - Y[0].y);
}

__global__ void k_addrev(const float2* __restrict__ wet, const float* __restrict__ fxp) {
  int idx = blockIdx.x * blockDim.x + threadIdx.x;
  if (idx >= 4 * S_LEN) return;
  int u = idx / S_LEN, i = idx - u * S_LEN;
  int b = u >> 1, ch = u & 1;
  float2 w2 = wet[(size_t)b*NFFT + i];
  float w = (ch == 0 ? w2.x : w2.y) * (1.f / (float)NFFT);
  float mparam = fxp[b*25 + 24];
  g_ms[idx] += (1.f - mparam) * g_fx[idx] + mparam * w;
}

// ------------------------------ final --------------------------------------
__global__ void k_final(const float2* __restrict__ gsb, float* __restrict__ out, long long off) {
  int idx = blockIdx.x * blockDim.x + threadIdx.x;
  if (idx >= 4 * S_LEN) return;
  int u = idx / S_LEN, i = idx - u * S_LEN;
  int b = u >> 1, ch = u & 1;
  int j = i + 1024; if (j > S_LEN - 1) j = S_LEN - 1;
  float2 gs2 = gsb[(size_t)b*NFFT + j];
  float gs = (ch == 0 ? gs2.x : gs2.y) * (1.f / (float)NFFT);
  float2 xm = g_xm[(size_t)b*S_LEN + i];
  float xv = (ch == 0 ? xm.x : xm.y);
  float makeup = g_mpd[b*26 + 24];
  float og = exp10f(g_mpd[b*26 + 25] * 0.05f);
  out[off + idx] = xv * exp10f((gs + makeup) * 0.05f) * og;
}

// ------------------------------ host side ----------------------------------
static inline int grid1(long long n) { return (int)((n + 255) / 256); }

// full 5-pass runs (generic kernels) for complex data already in a buffer
static float2* fft_run_big(float2* a, float2* b, int batch, float sg) {
  float2* src = a; float2* dst = b;
  int s = 1;
  for (int i = 0; i < 4; i++) {
    int total = batch * (NFFT >> 4);
    k_fft16<<<grid1(total), 256>>>(dst, src, NFFT, s, total, sg);
    float2* t = src; src = dst; dst = t;
    s <<= 4;
  }
  {
    int total = batch * (NFFT >> 3);
    k_fft8<<<grid1(total), 256>>>(dst, src, NFFT, s, total, sg);
    float2* t = src; src = dst; dst = t;
  }
  return src;
}

// passes 2..5 after a fused first pass already wrote `cur`
static float2* fft_rest_big(float2* cur, float2* other, int batch, float sg) {
  int s = 16;
  for (int i = 0; i < 3; i++) {
    int total = batch * (NFFT >> 4);
    k_fft16<<<grid1(total), 256>>>(other, cur, NFFT, s, total, sg);
    float2* t = cur; cur = other; other = t;
    s <<= 4;
  }
  {
    int total = batch * (NFFT >> 3);
    k_fft8<<<grid1(total), 256>>>(other, cur, NFFT, s, total, sg);
    float2* t = cur; cur = other; other = t;
  }
  return cur;
}

static float2* fft_run_nl(float2* a, float2* b, int batch, float sg) {
  float2* src = a; float2* dst = b;
  int s = 1;
  for (int i = 0; i < 4; i++) {
    int total = batch * (NL >> 4);
    k_fft16<<<grid1(total), 256>>>(dst, src, NL, s, total, sg);
    float2* t = src; src = dst; dst = t;
    s <<= 4;
  }
  {
    int total = batch * (NL >> 1);
    k_fft2<<<grid1(total), 256>>>(dst, src, NL, NL / s, s, total, sg);
    float2* t = src; src = dst; dst = t;
  }
  return src;
}

static float2* fft_rest_nl(float2* cur, float2* other, int batch, float sg) {
  int s = 16;
  for (int i = 0; i < 3; i++) {
    int total = batch * (NL >> 4);
    k_fft16<<<grid1(total), 256>>>(other, cur, NL, s, total, sg);
    float2* t = cur; cur = other; other = t;
    s <<= 4;
  }
  {
    int total = batch * (NL >> 1);
    k_fft2<<<grid1(total), 256>>>(other, cur, NL, NL / s, s, total, sg);
    float2* t = cur; cur = other; other = t;
  }
  return cur;
}

extern "C" void kernel_launch(void* const* d_in, const int* in_sizes, int n_in,
                              void* d_out, int out_size) {
  const float* tracks        = (const float*)d_in[0];
  const float* track_params  = (const float*)d_in[1];
  const float* fxp           = (const float*)d_in[2];
  const float* master_params = (const float*)d_in[3];
  const float* noise         = (const float*)d_in[4];
  const float* fb            = (const float*)d_in[5];
  float* out = (float*)d_out;

  float2 *A, *B, *C, *D, *E, *F;
  float *panbuf;
  cudaGetSymbolAddress((void**)&A, g_A);
  cudaGetSymbolAddress((void**)&B, g_B);
  cudaGetSymbolAddress((void**)&C, g_C);
  cudaGetSymbolAddress((void**)&D, g_D);
  cudaGetSymbolAddress((void**)&E, g_E);
  cudaGetSymbolAddress((void**)&F, g_F);
  cudaGetSymbolAddress((void**)&panbuf, g_pan);

  long long PAN = (long long)64 * S_LEN;
  long long moff = 0;
  float* pan = panbuf;
  if ((long long)out_size >= PAN + 4LL*S_LEN) { pan = out; moff = PAN; }

  k_prep<<<1, 256>>>(track_params, master_params);

  // ---- per-track chain: gain -> EQ -> comp -> pan (16 pairs) ----
  k_first_track<<<grid1((long long)NPAIR*(NFFT>>4)), 256>>>(A, tracks);
  float2* r = fft_rest_big(A, B, NPAIR, -1.f);                      // spectrum
  k_eqmul_pair<<<grid1((long long)NPAIR*(NFFT/2+1)), 256>>>(r);
  float2* t1 = fft_run_big(r, (r == A) ? B : A, NPAIR, 1.f);        // time (xN)
  float2* t1o = (t1 == A) ? B : A;
  k_compgc_track<<<grid1((long long)NPAIR*NFFT), 256>>>(t1, t1o);   // gc packed
  float2* r2 = fft_run_big(t1o, t1, NPAIR, -1.f);
  k_compmul_pair<<<grid1((long long)NPAIR*(NFFT/2+1)), 256>>>(r2);
  float2* t2 = fft_run_big(r2, (r2 == A) ? B : A, NPAIR, 1.f);      // g_s (xN)
  k_applypan<<<grid1((long long)NPAIR*S_LEN), 256>>>(t2, pan);
  k_mix<<<grid1((long long)4*S_LEN), 256>>>(pan);

  // ---- reverb IR build (NL domain) ----
  k_first_noise<<<grid1((long long)24*(NL>>4)), 256>>>(C, noise);
  float2* rn = fft_rest_nl(C, D, 24, -1.f);
  k_first_fb<<<grid1((long long)6*(NL>>4)), 256>>>(E, fb);
  float2* rf = fft_rest_nl(E, F, 6, -1.f);
  k_revmul<<<grid1((long long)24*NL), 256>>>(rn, rf);
  float2* ri = fft_run_nl(rn, (rn == C) ? D : C, 24, 1.f);
  k_buildir<<<grid1((long long)4*REVN), 256>>>(ri, fxp);

  // ---- wet convolution: FFT(fx_c + i*ir_c), product, paired inverse ----
  k_first_wet<<<grid1((long long)4*(NFFT>>4)), 256>>>(A);
  float2* rw = fft_rest_big(A, B, 4, -1.f);
  float2* rwo = (rw == A) ? B : A;
  k_wetprod<<<grid1((long long)2*(NFFT/2+1)), 256>>>(rw, rwo);
  float2* tw = fft_run_big(rwo, rw, 2, 1.f);                        // wet time (xN)
  k_addrev<<<grid1((long long)4*S_LEN), 256>>>(tw, fxp);

  // ---- master chain: gain -> EQ -> comp -> gain (2 pairs, shared filters) --
  k_first_master<<<grid1((long long)2*(NFFT>>4)), 256>>>(A);
  float2* m1 = fft_rest_big(A, B, 2, -1.f);
  k_eqmul_master<<<grid1((long long)2*NFFT), 256>>>(m1);
  float2* mt1 = fft_run_big(m1, (m1 == A) ? B : A, 2, 1.f);
  float2* mt1o = (mt1 == A) ? B : A;
  k_compgc_master<<<grid1((long long)2*NFFT), 256>>>(mt1, mt1o);
  float2* m2 = fft_run_big(mt1o, mt1, 2, -1.f);
  k_compmul_master<<<grid1((long long)2*NFFT), 256>>>(m2);
  float2* mt2 = fft_run_big(m2, (m2 == A) ? B : A, 2, 1.f);
  k_final<<<grid1((long long)4*S_LEN), 256>>>(mt2, out, moff);
}